// round 1
// baseline (speedup 1.0000x reference)
#include <cuda_runtime.h>
#include <math.h>

#define Bn 64
#define Cn 2048
#define Qn 128
#define Dn 128
#define MASK_VAL (-1e30f)

// ---------------- scratch (static device allocations; no runtime alloc) ----------------
__device__ float g_score[(size_t)Bn*Cn*Qn];     // 67MB raw trilinear scores
__device__ float g_Beff [(size_t)Bn*Dn*Qn];     // transformed qfeats for score GEMM
__device__ float g_bq   [Bn*Qn];
__device__ float g_rowmax[Bn*Cn];
__device__ float g_rowsum[Bn*Cn];
__device__ float g_colpm[Bn*16*Qn];
__device__ float g_colps[Bn*16*Qn];
__device__ float g_colmax[Bn*Qn];
__device__ float g_colsum[Bn*Qn];
__device__ float g_tmp_part[(size_t)Bn*4*Qn*Dn];
__device__ float g_tmp [(size_t)Bn*Qn*Dn];
__device__ float g_bias2[Bn*Dn];
__device__ float g_c2q [(size_t)Bn*Cn*Dn];      // 67MB
__device__ float g_q2c [(size_t)Bn*Cn*Dn];      // 67MB
__device__ float g_feats[(size_t)Bn*Cn*Dn];     // 67MB
__device__ float g_cqaWT[512*128];              // cqa_W transposed to k-major
__device__ float g_ccWT [128*128];              // cc_W (first half) transposed to k-major

// ---------------- prep: weight transposes ----------------
__global__ void k_prepW(const float* __restrict__ cqaW, const float* __restrict__ ccW){
  int tid = blockIdx.x*blockDim.x + threadIdx.x;
  int stride = gridDim.x*blockDim.x;
  for (int idx = tid; idx < 512*128; idx += stride){
    int k = idx >> 7, n = idx & 127;
    g_cqaWT[idx] = cqaW[n*512 + k];
  }
  for (int idx = tid; idx < 128*128; idx += stride){
    int k = idx >> 7, n = idx & 127;
    g_ccWT[idx] = ccW[n*256 + k];
  }
}

// ---------------- prep: Beff[b][d][q] = qf[b][q][d]*w4mlu[d] + w4C[d] ----------------
__global__ void __launch_bounds__(128) k_beff(const float* __restrict__ qf,
                                              const float* __restrict__ w4mlu,
                                              const float* __restrict__ w4C){
  int b = blockIdx.x, tid = threadIdx.x;
  __shared__ float s[64][129];
  for (int q0 = 0; q0 < Qn; q0 += 64){
    for (int r = 0; r < 64; r++)
      s[r][tid] = qf[((size_t)b*Qn + q0 + r)*Dn + tid];
    __syncthreads();
    for (int it = 0; it < 64; it++){
      int idx = it*128 + tid;
      int d = idx >> 6, q = idx & 63;
      g_Beff[(size_t)b*Dn*Qn + (size_t)d*Qn + q0 + q] = s[q][d]*w4mlu[d] + w4C[d];
    }
    __syncthreads();
  }
}

// ---------------- prep: bq, pooled softmax, per-batch cc bias ----------------
__global__ void __launch_bounds__(128) k_pool(const float* __restrict__ qf,
                                              const float* __restrict__ w4Q,
                                              const float* __restrict__ wp,
                                              const float* __restrict__ qmask,
                                              const float* __restrict__ ccW,
                                              const float* __restrict__ ccb){
  int b = blockIdx.x, tid = threadIdx.x;
  __shared__ float red[128];
  __shared__ float alpha[128];
  __shared__ float pooled[128];
  const float* qrow = qf + ((size_t)b*Qn + tid)*Dn;
  float bq = 0.f, lg = 0.f;
  for (int d = 0; d < Dn; d++){ float v = qrow[d]; bq += v*w4Q[d]; lg += v*wp[d]; }
  g_bq[b*Qn + tid] = bq;
  float x = lg + (1.f - qmask[b*Qn + tid])*MASK_VAL;
  red[tid] = x; __syncthreads();
  for (int s = 64; s > 0; s >>= 1){ if (tid < s) red[tid] = fmaxf(red[tid], red[tid+s]); __syncthreads(); }
  float m = red[0]; __syncthreads();
  float e = __expf(x - m);
  red[tid] = e; __syncthreads();
  for (int s = 64; s > 0; s >>= 1){ if (tid < s) red[tid] += red[tid+s]; __syncthreads(); }
  float ssum = red[0];
  alpha[tid] = e / ssum;
  __syncthreads();
  float p = 0.f;
  for (int q = 0; q < Qn; q++) p += qf[((size_t)b*Qn + q)*Dn + tid]*alpha[q];
  pooled[tid] = p; __syncthreads();
  float acc = ccb[tid];
  for (int k = 0; k < Dn; k++) acc += pooled[k]*ccW[tid*256 + 128 + k];
  g_bias2[b*Dn + tid] = acc;
}

// ---------------- score GEMM: S = V @ Beff + bq ----------------
__global__ void __launch_bounds__(256) k_score(const float* __restrict__ vfeats){
  int b  = blockIdx.y;
  int m0 = blockIdx.x*128;
  const float* A  = vfeats + (size_t)b*Cn*Dn;
  const float* Bm = g_Beff + (size_t)b*Dn*Qn;
  float* Sout = g_score + (size_t)b*Cn*Qn;
  __shared__ float As[16][128];
  __shared__ float Bs[16][128];
  int tid = threadIdx.x;
  int tx = tid & 15, ty = tid >> 4;
  float acc[8][8] = {};
  for (int k0 = 0; k0 < Dn; k0 += 16){
    int acol = tid & 15, arow0 = tid >> 4;
    #pragma unroll
    for (int i = 0; i < 8; i++){
      int row = arow0 + i*16;
      As[acol][row] = A[(size_t)(m0 + row)*Dn + k0 + acol];
    }
    int krow = tid >> 4; int n0 = (tid & 15)*8;
    *(float4*)&Bs[krow][n0]   = *(const float4*)&Bm[(size_t)(k0 + krow)*Qn + n0];
    *(float4*)&Bs[krow][n0+4] = *(const float4*)&Bm[(size_t)(k0 + krow)*Qn + n0 + 4];
    __syncthreads();
    #pragma unroll
    for (int k = 0; k < 16; k++){
      float4 a0 = *(const float4*)&As[k][ty*8];
      float4 a1 = *(const float4*)&As[k][ty*8+4];
      float4 b0 = *(const float4*)&Bs[k][tx*8];
      float4 b1 = *(const float4*)&Bs[k][tx*8+4];
      float a[8]  = {a0.x,a0.y,a0.z,a0.w,a1.x,a1.y,a1.z,a1.w};
      float bb[8] = {b0.x,b0.y,b0.z,b0.w,b1.x,b1.y,b1.z,b1.w};
      #pragma unroll
      for (int i = 0; i < 8; i++)
        #pragma unroll
        for (int j = 0; j < 8; j++) acc[i][j] = fmaf(a[i], bb[j], acc[i][j]);
    }
    __syncthreads();
  }
  #pragma unroll
  for (int i = 0; i < 8; i++){
    int m = m0 + ty*8 + i;
    #pragma unroll
    for (int j = 0; j < 8; j += 4){
      int n = tx*8 + j;
      float4 o;
      o.x = acc[i][j]   + g_bq[b*Qn + n];
      o.y = acc[i][j+1] + g_bq[b*Qn + n + 1];
      o.z = acc[i][j+2] + g_bq[b*Qn + n + 2];
      o.w = acc[i][j+3] + g_bq[b*Qn + n + 3];
      *(float4*)&Sout[(size_t)m*Qn + n] = o;
    }
  }
}

// ---------------- row softmax stats (over Q) ----------------
__global__ void __launch_bounds__(256) k_rowstats(const float* __restrict__ qmask){
  int gw = (blockIdx.x*256 + threadIdx.x) >> 5;  // row index in [0, B*C)
  int lane = threadIdx.x & 31;
  if (gw >= Bn*Cn) return;
  int b = gw / Cn;
  const float* Sr = g_score + (size_t)gw*Qn;
  float x[4]; float m = -INFINITY;
  #pragma unroll
  for (int i = 0; i < 4; i++){
    int q = lane + i*32;
    x[i] = Sr[q] + (1.f - qmask[b*Qn + q])*MASK_VAL;
    m = fmaxf(m, x[i]);
  }
  #pragma unroll
  for (int o = 16; o > 0; o >>= 1) m = fmaxf(m, __shfl_xor_sync(0xffffffffu, m, o));
  float s = 0.f;
  #pragma unroll
  for (int i = 0; i < 4; i++) s += __expf(x[i] - m);
  #pragma unroll
  for (int o = 16; o > 0; o >>= 1) s += __shfl_xor_sync(0xffffffffu, s, o);
  if (lane == 0){ g_rowmax[gw] = m; g_rowsum[gw] = s; }
}

// ---------------- column softmax stats (over C), 16-way split ----------------
__global__ void __launch_bounds__(128) k_colstats(const float* __restrict__ vmask){
  int b = blockIdx.y, ch = blockIdx.x, q = threadIdx.x;
  const float* Sb = g_score + (size_t)b*Cn*Qn;
  float m = -INFINITY, s = 0.f;
  int c0 = ch*128;
  for (int c = c0; c < c0 + 128; c++){
    float x = Sb[(size_t)c*Qn + q] + (1.f - vmask[b*Cn + c])*MASK_VAL;
    float nm = fmaxf(m, x);
    s = s*__expf(m - nm) + __expf(x - nm);
    m = nm;
  }
  g_colpm[(b*16 + ch)*Qn + q] = m;
  g_colps[(b*16 + ch)*Qn + q] = s;
}

__global__ void __launch_bounds__(128) k_colcombine(){
  int b = blockIdx.x, q = threadIdx.x;
  float m = -INFINITY, s = 0.f;
  for (int ch = 0; ch < 16; ch++){
    float pm = g_colpm[(b*16 + ch)*Qn + q];
    float ps = g_colps[(b*16 + ch)*Qn + q];
    float nm = fmaxf(m, pm);
    s = s*__expf(m - nm) + ps*__expf(pm - nm);
    m = nm;
  }
  g_colmax[b*Qn + q] = m;
  g_colsum[b*Qn + q] = s;
}

// ---------------- tmp = score_t^T @ V  (split-K over C, 4 chunks) ----------------
__global__ void __launch_bounds__(256) k_tmp_part(const float* __restrict__ vfeats,
                                                  const float* __restrict__ vmask){
  int b = blockIdx.y, ch = blockIdx.x;
  const float* Sb = g_score + (size_t)b*Cn*Qn;
  const float* V  = vfeats  + (size_t)b*Cn*Dn;
  __shared__ float As[16][128]; // [k=c][m=q]  (exp-transformed, unnormalized)
  __shared__ float Bs[16][128]; // [k=c][n=d]
  __shared__ float cm[128];
  int tid = threadIdx.x;
  if (tid < 128) cm[tid] = g_colmax[b*Qn + tid];
  __syncthreads();
  int tx = tid & 15, ty = tid >> 4;
  float acc[8][8] = {};
  int cbase = ch*512;
  for (int kt = 0; kt < 512; kt += 16){
    int krow = tid >> 4; int e0 = (tid & 15)*8;
    int c = cbase + kt + krow;
    float mv = (1.f - vmask[b*Cn + c])*MASK_VAL;
    float4 s0 = *(const float4*)&Sb[(size_t)c*Qn + e0];
    float4 s1 = *(const float4*)&Sb[(size_t)c*Qn + e0 + 4];
    As[krow][e0+0] = __expf(s0.x + mv - cm[e0+0]);
    As[krow][e0+1] = __expf(s0.y + mv - cm[e0+1]);
    As[krow][e0+2] = __expf(s0.z + mv - cm[e0+2]);
    As[krow][e0+3] = __expf(s0.w + mv - cm[e0+3]);
    As[krow][e0+4] = __expf(s1.x + mv - cm[e0+4]);
    As[krow][e0+5] = __expf(s1.y + mv - cm[e0+5]);
    As[krow][e0+6] = __expf(s1.z + mv - cm[e0+6]);
    As[krow][e0+7] = __expf(s1.w + mv - cm[e0+7]);
    *(float4*)&Bs[krow][e0]   = *(const float4*)&V[(size_t)c*Dn + e0];
    *(float4*)&Bs[krow][e0+4] = *(const float4*)&V[(size_t)c*Dn + e0 + 4];
    __syncthreads();
    #pragma unroll
    for (int k = 0; k < 16; k++){
      float4 a0 = *(const float4*)&As[k][ty*8];
      float4 a1 = *(const float4*)&As[k][ty*8+4];
      float4 b0 = *(const float4*)&Bs[k][tx*8];
      float4 b1 = *(const float4*)&Bs[k][tx*8+4];
      float a[8]  = {a0.x,a0.y,a0.z,a0.w,a1.x,a1.y,a1.z,a1.w};
      float bb[8] = {b0.x,b0.y,b0.z,b0.w,b1.x,b1.y,b1.z,b1.w};
      #pragma unroll
      for (int i = 0; i < 8; i++)
        #pragma unroll
        for (int j = 0; j < 8; j++) acc[i][j] = fmaf(a[i], bb[j], acc[i][j]);
    }
    __syncthreads();
  }
  float* P = g_tmp_part + (size_t)(b*4 + ch)*Qn*Dn;
  #pragma unroll
  for (int i = 0; i < 8; i++){
    int m = ty*8 + i;
    #pragma unroll
    for (int j = 0; j < 8; j += 4)
      *(float4*)&P[(size_t)m*Dn + tx*8 + j] = *(float4*)&acc[i][j];
  }
}

__global__ void __launch_bounds__(256) k_tmp_reduce(){
  int idx = blockIdx.x*256 + threadIdx.x;           // [0, B*Q*D)
  int b = idx >> 14;                                 // Q*D = 16384
  int r = idx & 16383;
  int q = r >> 7;
  size_t base = (size_t)b*4*Qn*Dn + r;
  float s = g_tmp_part[base] + g_tmp_part[base + Qn*Dn]
          + g_tmp_part[base + 2*Qn*Dn] + g_tmp_part[base + 3*Qn*Dn];
  g_tmp[idx] = s / g_colsum[b*Qn + q];
}

// ---------------- c2q = P @ qf ; q2c = P @ tmp (shared A tile) ----------------
__global__ void __launch_bounds__(256) k_c2q(const float* __restrict__ qfeats,
                                             const float* __restrict__ qmask){
  int b = blockIdx.y; int m0 = blockIdx.x*64;
  const float* Sb = g_score + (size_t)b*Cn*Qn;
  const float* QF = qfeats  + (size_t)b*Qn*Dn;
  const float* TP = g_tmp   + (size_t)b*Qn*Dn;
  __shared__ float As[16][65];   // [k=q][m=c], padded
  __shared__ float B1[16][128];
  __shared__ float B2[16][128];
  __shared__ float qm[128];
  __shared__ float rm[64], ri[64];
  int tid = threadIdx.x;
  if (tid < 128) qm[tid] = (1.f - qmask[b*Qn + tid])*MASK_VAL;
  if (tid < 64){
    rm[tid] = g_rowmax[b*Cn + m0 + tid];
    ri[tid] = 1.f / g_rowsum[b*Cn + m0 + tid];
  }
  __syncthreads();
  int tx = tid & 15, ty = tid >> 4;
  float acc1[4][8] = {}, acc2[4][8] = {};
  for (int k0 = 0; k0 < Qn; k0 += 16){
    int am = tid >> 2; int ak0 = (tid & 3)*4;
    float4 s = *(const float4*)&Sb[(size_t)(m0 + am)*Qn + k0 + ak0];
    float mm = rm[am]; float rr = ri[am];
    As[ak0+0][am] = __expf(s.x + qm[k0+ak0+0] - mm)*rr;
    As[ak0+1][am] = __expf(s.y + qm[k0+ak0+1] - mm)*rr;
    As[ak0+2][am] = __expf(s.z + qm[k0+ak0+2] - mm)*rr;
    As[ak0+3][am] = __expf(s.w + qm[k0+ak0+3] - mm)*rr;
    int krow = tid >> 4; int n0 = (tid & 15)*8;
    *(float4*)&B1[krow][n0]   = *(const float4*)&QF[(size_t)(k0 + krow)*Dn + n0];
    *(float4*)&B1[krow][n0+4] = *(const float4*)&QF[(size_t)(k0 + krow)*Dn + n0 + 4];
    *(float4*)&B2[krow][n0]   = *(const float4*)&TP[(size_t)(k0 + krow)*Dn + n0];
    *(float4*)&B2[krow][n0+4] = *(const float4*)&TP[(size_t)(k0 + krow)*Dn + n0 + 4];
    __syncthreads();
    #pragma unroll
    for (int k = 0; k < 16; k++){
      float a[4];
      #pragma unroll
      for (int i = 0; i < 4; i++) a[i] = As[k][ty*4 + i];
      float4 c0 = *(const float4*)&B1[k][tx*8];
      float4 c1 = *(const float4*)&B1[k][tx*8+4];
      float4 d0 = *(const float4*)&B2[k][tx*8];
      float4 d1 = *(const float4*)&B2[k][tx*8+4];
      float b1[8] = {c0.x,c0.y,c0.z,c0.w,c1.x,c1.y,c1.z,c1.w};
      float b2[8] = {d0.x,d0.y,d0.z,d0.w,d1.x,d1.y,d1.z,d1.w};
      #pragma unroll
      for (int i = 0; i < 4; i++)
        #pragma unroll
        for (int j = 0; j < 8; j++){
          acc1[i][j] = fmaf(a[i], b1[j], acc1[i][j]);
          acc2[i][j] = fmaf(a[i], b2[j], acc2[i][j]);
        }
    }
    __syncthreads();
  }
  float* C1 = g_c2q + ((size_t)b*Cn + m0)*Dn;
  float* C2 = g_q2c + ((size_t)b*Cn + m0)*Dn;
  #pragma unroll
  for (int i = 0; i < 4; i++){
    int m = ty*4 + i;
    #pragma unroll
    for (int j = 0; j < 8; j += 4){
      *(float4*)&C1[(size_t)m*Dn + tx*8 + j] = *(float4*)&acc1[i][j];
      *(float4*)&C2[(size_t)m*Dn + tx*8 + j] = *(float4*)&acc2[i][j];
    }
  }
}

// ---------------- feats = [v, c2q, v*c2q, v*q2c] @ cqa_W^T + cqa_b ----------------
__global__ void __launch_bounds__(256) k_feats(const float* __restrict__ vfeats,
                                               const float* __restrict__ cqa_b){
  size_t m0 = (size_t)blockIdx.x*128;
  __shared__ float As[16][128];
  __shared__ float Bs[16][128];
  int tid = threadIdx.x;
  int tx = tid & 15, ty = tid >> 4;
  float acc[8][8] = {};
  for (int it = 0; it < 32; it++){
    int src = it >> 3; int kl0 = (it & 7)*16;
    int acol = tid & 15, arow0 = tid >> 4;
    #pragma unroll
    for (int i = 0; i < 8; i++){
      int row = arow0 + i*16;
      size_t off = (m0 + row)*(size_t)Dn + kl0 + acol;
      float v;
      if (src == 0)      v = vfeats[off];
      else if (src == 1) v = g_c2q[off];
      else if (src == 2) v = vfeats[off]*g_c2q[off];
      else               v = vfeats[off]*g_q2c[off];
      As[acol][row] = v;
    }
    int krow = tid >> 4; int n0 = (tid & 15)*8;
    int kk = it*16 + krow;
    *(float4*)&Bs[krow][n0]   = *(const float4*)&g_cqaWT[kk*128 + n0];
    *(float4*)&Bs[krow][n0+4] = *(const float4*)&g_cqaWT[kk*128 + n0 + 4];
    __syncthreads();
    #pragma unroll
    for (int k = 0; k < 16; k++){
      float4 a0 = *(const float4*)&As[k][ty*8];
      float4 a1 = *(const float4*)&As[k][ty*8+4];
      float4 b0 = *(const float4*)&Bs[k][tx*8];
      float4 b1 = *(const float4*)&Bs[k][tx*8+4];
      float a[8]  = {a0.x,a0.y,a0.z,a0.w,a1.x,a1.y,a1.z,a1.w};
      float bb[8] = {b0.x,b0.y,b0.z,b0.w,b1.x,b1.y,b1.z,b1.w};
      #pragma unroll
      for (int i = 0; i < 8; i++)
        #pragma unroll
        for (int j = 0; j < 8; j++) acc[i][j] = fmaf(a[i], bb[j], acc[i][j]);
    }
    __syncthreads();
  }
  #pragma unroll
  for (int i = 0; i < 8; i++){
    size_t m = m0 + ty*8 + i;
    #pragma unroll
    for (int j = 0; j < 8; j += 4){
      int n = tx*8 + j;
      float4 o;
      o.x = acc[i][j]   + cqa_b[n];
      o.y = acc[i][j+1] + cqa_b[n+1];
      o.z = acc[i][j+2] + cqa_b[n+2];
      o.w = acc[i][j+3] + cqa_b[n+3];
      *(float4*)&g_feats[m*Dn + n] = o;
    }
  }
}

// ---------------- out = relu(feats @ ccW1^T + bias2[b]) ----------------
__global__ void __launch_bounds__(256) k_out(float* __restrict__ out){
  size_t m0 = (size_t)blockIdx.x*128;
  __shared__ float As[16][128];
  __shared__ float Bs[16][128];
  int tid = threadIdx.x;
  int tx = tid & 15, ty = tid >> 4;
  float acc[8][8] = {};
  for (int k0 = 0; k0 < 128; k0 += 16){
    int acol = tid & 15, arow0 = tid >> 4;
    #pragma unroll
    for (int i = 0; i < 8; i++){
      int row = arow0 + i*16;
      As[acol][row] = g_feats[(m0 + row)*(size_t)Dn + k0 + acol];
    }
    int krow = tid >> 4; int n0 = (tid & 15)*8;
    *(float4*)&Bs[krow][n0]   = *(const float4*)&g_ccWT[(k0 + krow)*128 + n0];
    *(float4*)&Bs[krow][n0+4] = *(const float4*)&g_ccWT[(k0 + krow)*128 + n0 + 4];
    __syncthreads();
    #pragma unroll
    for (int k = 0; k < 16; k++){
      float4 a0 = *(const float4*)&As[k][ty*8];
      float4 a1 = *(const float4*)&As[k][ty*8+4];
      float4 b0 = *(const float4*)&Bs[k][tx*8];
      float4 b1 = *(const float4*)&Bs[k][tx*8+4];
      float a[8]  = {a0.x,a0.y,a0.z,a0.w,a1.x,a1.y,a1.z,a1.w};
      float bb[8] = {b0.x,b0.y,b0.z,b0.w,b1.x,b1.y,b1.z,b1.w};
      #pragma unroll
      for (int i = 0; i < 8; i++)
        #pragma unroll
        for (int j = 0; j < 8; j++) acc[i][j] = fmaf(a[i], bb[j], acc[i][j]);
    }
    __syncthreads();
  }
  #pragma unroll
  for (int i = 0; i < 8; i++){
    size_t m = m0 + ty*8 + i;
    int b = (int)(m >> 11);  // / 2048
    #pragma unroll
    for (int j = 0; j < 8; j += 4){
      int n = tx*8 + j;
      float4 o;
      o.x = fmaxf(acc[i][j]   + g_bias2[b*Dn + n],     0.f);
      o.y = fmaxf(acc[i][j+1] + g_bias2[b*Dn + n + 1], 0.f);
      o.z = fmaxf(acc[i][j+2] + g_bias2[b*Dn + n + 2], 0.f);
      o.w = fmaxf(acc[i][j+3] + g_bias2[b*Dn + n + 3], 0.f);
      *(float4*)&out[m*Dn + n] = o;
    }
  }
}

// ---------------- launch ----------------
extern "C" void kernel_launch(void* const* d_in, const int* in_sizes, int n_in,
                              void* d_out, int out_size){
  const float* vfeats = (const float*)d_in[0];
  const float* qfeats = (const float*)d_in[1];
  const float* vmask  = (const float*)d_in[2];
  const float* qmask  = (const float*)d_in[3];
  const float* w4C    = (const float*)d_in[4];
  const float* w4Q    = (const float*)d_in[5];
  const float* w4mlu  = (const float*)d_in[6];
  const float* cqa_W  = (const float*)d_in[7];
  const float* cqa_b  = (const float*)d_in[8];
  const float* wp     = (const float*)d_in[9];
  const float* cc_W   = (const float*)d_in[10];
  const float* cc_b   = (const float*)d_in[11];
  float* out = (float*)d_out;

  k_prepW<<<128, 256>>>(cqa_W, cc_W);
  k_beff<<<Bn, 128>>>(qfeats, w4mlu, w4C);
  k_pool<<<Bn, 128>>>(qfeats, w4Q, wp, qmask, cc_W, cc_b);
  k_score<<<dim3(Cn/128, Bn), 256>>>(vfeats);
  k_rowstats<<<(Bn*Cn)/8, 256>>>(qmask);
  k_colstats<<<dim3(16, Bn), 128>>>(vmask);
  k_colcombine<<<Bn, 128>>>();
  k_tmp_part<<<dim3(4, Bn), 256>>>(vfeats, vmask);
  k_tmp_reduce<<<(Bn*Qn*Dn)/256, 256>>>();
  k_c2q<<<dim3(Cn/64, Bn), 256>>>(qfeats, qmask);
  k_feats<<<(Bn*Cn)/128, 256>>>(vfeats, cqa_b);
  k_out<<<(Bn*Cn)/128, 256>>>(out);
}

// round 5
// speedup vs baseline: 1.1177x; 1.1177x over previous
#include <cuda_runtime.h>
#include <math.h>

#define Bn 64
#define Cn 2048
#define Qn 128
#define Dn 128
#define MASK_VAL (-1e30f)

// ---------------- scratch ----------------
__device__ float g_score[(size_t)Bn*Cn*Qn];
__device__ float g_Beff [(size_t)Bn*Dn*Qn];
__device__ float g_bq   [Bn*Qn];
__device__ float g_rowmax[Bn*Cn];
__device__ float g_rowsum[Bn*Cn];
__device__ float g_colpm[Bn*16*Qn];
__device__ float g_colps[Bn*16*Qn];
__device__ float g_colmax[Bn*Qn];
__device__ float g_colsum[Bn*Qn];
__device__ float g_tmp_part[(size_t)Bn*4*Qn*Dn];
__device__ float g_tmp [(size_t)Bn*Qn*Dn];
__device__ float g_bias2[Bn*Dn];
__device__ float g_c2q [(size_t)Bn*Cn*Dn];
__device__ float g_q2c [(size_t)Bn*Cn*Dn];
__device__ float g_feats[(size_t)Bn*Cn*Dn];
__device__ float g_cqaWT[512*128];
__device__ float g_ccWT [128*128];

// ---------------- tf32 helpers ----------------
__device__ __forceinline__ unsigned cvt_tf32(float x){
  unsigned u; asm("cvt.rna.tf32.f32 %0, %1;" : "=r"(u) : "f"(x)); return u;
}
__device__ __forceinline__ float tf32_hi(float x){ return __uint_as_float(cvt_tf32(x)); }

#define MMA_TF32(D, A0,A1,A2,A3, B0,B1) \
  asm volatile("mma.sync.aligned.m16n8k8.row.col.f32.tf32.tf32.f32 " \
      "{%0,%1,%2,%3}, {%4,%5,%6,%7}, {%8,%9}, {%0,%1,%2,%3};" \
      : "+f"(D[0]), "+f"(D[1]), "+f"(D[2]), "+f"(D[3]) \
      : "r"(A0), "r"(A1), "r"(A2), "r"(A3), "r"(B0), "r"(B1))

// Per-warp 32x64 tile MMA over a k16 chunk.
// As: [128][20] rows=m, cols = permuted k (colp = (k%4)*4 + k/4)
// Bs: [128][20] rows=n, cols = permuted k
__device__ __forceinline__ void mma_k16(const float (*As)[20], const float (*Bs)[20],
                                        float acc[2][8][4], int mb, int nb, int grp, int qd){
  float4 va[2][2];
  #pragma unroll
  for (int mi = 0; mi < 2; mi++){
    int r = mb + mi*16 + grp;
    va[mi][0] = *(const float4*)&As[r][qd*4];
    va[mi][1] = *(const float4*)&As[r+8][qd*4];
  }
  float4 vb[8];
  #pragma unroll
  for (int ni = 0; ni < 8; ni++){
    int n = nb + ni*8 + grp;
    vb[ni] = *(const float4*)&Bs[n][qd*4];
  }
  #pragma unroll
  for (int mi = 0; mi < 2; mi++)
    #pragma unroll
    for (int ni = 0; ni < 8; ni++){
      MMA_TF32(acc[mi][ni],
        __float_as_uint(va[mi][0].x), __float_as_uint(va[mi][1].x),
        __float_as_uint(va[mi][0].y), __float_as_uint(va[mi][1].y),
        __float_as_uint(vb[ni].x),    __float_as_uint(vb[ni].y));
      MMA_TF32(acc[mi][ni],
        __float_as_uint(va[mi][0].z), __float_as_uint(va[mi][1].z),
        __float_as_uint(va[mi][0].w), __float_as_uint(va[mi][1].w),
        __float_as_uint(vb[ni].z),    __float_as_uint(vb[ni].w));
    }
}

// ---------------- prep kernels ----------------
__global__ void k_prepW(const float* __restrict__ cqaW, const float* __restrict__ ccW){
  int tid = blockIdx.x*blockDim.x + threadIdx.x;
  int stride = gridDim.x*blockDim.x;
  for (int idx = tid; idx < 512*128; idx += stride){
    int k = idx >> 7, n = idx & 127;
    g_cqaWT[idx] = cqaW[n*512 + k];
  }
  for (int idx = tid; idx < 128*128; idx += stride){
    int k = idx >> 7, n = idx & 127;
    g_ccWT[idx] = ccW[n*256 + k];
  }
}

__global__ void __launch_bounds__(128) k_beff(const float* __restrict__ qf,
                                              const float* __restrict__ w4mlu,
                                              const float* __restrict__ w4C){
  int b = blockIdx.x, tid = threadIdx.x;
  __shared__ float s[64][129];
  for (int q0 = 0; q0 < Qn; q0 += 64){
    for (int r = 0; r < 64; r++)
      s[r][tid] = qf[((size_t)b*Qn + q0 + r)*Dn + tid];
    __syncthreads();
    for (int it = 0; it < 64; it++){
      int idx = it*128 + tid;
      int d = idx >> 6, q = idx & 63;
      g_Beff[(size_t)b*Dn*Qn + (size_t)d*Qn + q0 + q] = s[q][d]*w4mlu[d] + w4C[d];
    }
    __syncthreads();
  }
}

__global__ void __launch_bounds__(128) k_pool(const float* __restrict__ qf,
                                              const float* __restrict__ w4Q,
                                              const float* __restrict__ wp,
                                              const float* __restrict__ qmask,
                                              const float* __restrict__ ccW,
                                              const float* __restrict__ ccb){
  int b = blockIdx.x, tid = threadIdx.x;
  __shared__ float red[128];
  __shared__ float alpha[128];
  __shared__ float pooled[128];
  const float* qrow = qf + ((size_t)b*Qn + tid)*Dn;
  float bq = 0.f, lg = 0.f;
  for (int d = 0; d < Dn; d++){ float v = qrow[d]; bq += v*w4Q[d]; lg += v*wp[d]; }
  g_bq[b*Qn + tid] = bq;
  float x = lg + (1.f - qmask[b*Qn + tid])*MASK_VAL;
  red[tid] = x; __syncthreads();
  for (int s = 64; s > 0; s >>= 1){ if (tid < s) red[tid] = fmaxf(red[tid], red[tid+s]); __syncthreads(); }
  float m = red[0]; __syncthreads();
  float e = __expf(x - m);
  red[tid] = e; __syncthreads();
  for (int s = 64; s > 0; s >>= 1){ if (tid < s) red[tid] += red[tid+s]; __syncthreads(); }
  float ssum = red[0];
  alpha[tid] = e / ssum;
  __syncthreads();
  float p = 0.f;
  for (int q = 0; q < Qn; q++) p += qf[((size_t)b*Qn + q)*Dn + tid]*alpha[q];
  pooled[tid] = p; __syncthreads();
  float acc = ccb[tid];
  for (int k = 0; k < Dn; k++) acc += pooled[k]*ccW[tid*256 + 128 + k];
  g_bias2[b*Dn + tid] = acc;
}

// ---------------- score GEMM (tf32 hi/lo residual): S = V @ Beff + bq ----------------
__global__ void __launch_bounds__(256,2) k_score(const float* __restrict__ vfeats){
  int b  = blockIdx.y;
  int m0 = blockIdx.x*128;
  const float* A  = vfeats + (size_t)b*Cn*Dn;
  const float* Bm = g_Beff + (size_t)b*Dn*Qn;
  float* Sout = g_score + (size_t)b*Cn*Qn;
  __shared__ float Ah[128][20], Al[128][20], Bh[128][20], Bl[128][20];
  __shared__ float bqs[128];
  int tid = threadIdx.x;
  if (tid < 128) bqs[tid] = g_bq[b*Qn + tid];
  int warp = tid >> 5, lane = tid & 31;
  int WM = warp >> 1, WN = warp & 1;
  int grp = lane >> 2, qd = lane & 3;
  int mb = WM*32, nb = WN*64;
  float acc[2][8][4] = {};
  int arow = tid >> 1, aj0 = (tid & 1)*2;
  int bkl = tid >> 4, bseg = tid & 15;
  int bcolp = (bkl & 3)*4 + (bkl >> 2);
  for (int k0 = 0; k0 < Dn; k0 += 16){
    #pragma unroll
    for (int jj = 0; jj < 2; jj++){
      int j = aj0 + jj;
      float4 v = *(const float4*)&A[(size_t)(m0 + arow)*Dn + k0 + j*4];
      float h;
      h = tf32_hi(v.x); Ah[arow][0+j] = h;  Al[arow][0+j]  = tf32_hi(v.x - h);
      h = tf32_hi(v.y); Ah[arow][4+j] = h;  Al[arow][4+j]  = tf32_hi(v.y - h);
      h = tf32_hi(v.z); Ah[arow][8+j] = h;  Al[arow][8+j]  = tf32_hi(v.z - h);
      h = tf32_hi(v.w); Ah[arow][12+j] = h; Al[arow][12+j] = tf32_hi(v.w - h);
    }
    {
      const float* src = &Bm[(size_t)(k0 + bkl)*Qn + bseg*8];
      float4 v0 = *(const float4*)&src[0];
      float4 v1 = *(const float4*)&src[4];
      int n0 = bseg*8;
      float vv[8] = {v0.x,v0.y,v0.z,v0.w,v1.x,v1.y,v1.z,v1.w};
      #pragma unroll
      for (int e = 0; e < 8; e++){
        float h = tf32_hi(vv[e]);
        Bh[n0+e][bcolp] = h; Bl[n0+e][bcolp] = tf32_hi(vv[e]-h);
      }
    }
    __syncthreads();
    mma_k16(Ah, Bh, acc, mb, nb, grp, qd);
    mma_k16(Al, Bh, acc, mb, nb, grp, qd);
    mma_k16(Ah, Bl, acc, mb, nb, grp, qd);
    __syncthreads();
  }
  #pragma unroll
  for (int mi = 0; mi < 2; mi++){
    int r = m0 + mb + mi*16 + grp;
    #pragma unroll
    for (int ni = 0; ni < 8; ni++){
      int col = nb + ni*8 + qd*2;
      float2 w0 = make_float2(acc[mi][ni][0] + bqs[col], acc[mi][ni][1] + bqs[col+1]);
      float2 w1 = make_float2(acc[mi][ni][2] + bqs[col], acc[mi][ni][3] + bqs[col+1]);
      *(float2*)&Sout[(size_t)r*Qn + col] = w0;
      *(float2*)&Sout[(size_t)(r+8)*Qn + col] = w1;
    }
  }
}

// ---------------- softmax stats ----------------
__global__ void __launch_bounds__(256) k_rowstats(const float* __restrict__ qmask){
  int gw = (blockIdx.x*256 + threadIdx.x) >> 5;
  int lane = threadIdx.x & 31;
  if (gw >= Bn*Cn) return;
  int b = gw / Cn;
  const float* Sr = g_score + (size_t)gw*Qn;
  float x[4]; float m = -INFINITY;
  #pragma unroll
  for (int i = 0; i < 4; i++){
    int q = lane + i*32;
    x[i] = Sr[q] + (1.f - qmask[b*Qn + q])*MASK_VAL;
    m = fmaxf(m, x[i]);
  }
  #pragma unroll
  for (int o = 16; o > 0; o >>= 1) m = fmaxf(m, __shfl_xor_sync(0xffffffffu, m, o));
  float s = 0.f;
  #pragma unroll
  for (int i = 0; i < 4; i++) s += __expf(x[i] - m);
  #pragma unroll
  for (int o = 16; o > 0; o >>= 1) s += __shfl_xor_sync(0xffffffffu, s, o);
  if (lane == 0){ g_rowmax[gw] = m; g_rowsum[gw] = s; }
}

__global__ void __launch_bounds__(128) k_colstats(const float* __restrict__ vmask){
  int b = blockIdx.y, ch = blockIdx.x, q = threadIdx.x;
  const float* Sb = g_score + (size_t)b*Cn*Qn;
  float m = -INFINITY, s = 0.f;
  int c0 = ch*128;
  for (int c = c0; c < c0 + 128; c++){
    float x = Sb[(size_t)c*Qn + q] + (1.f - vmask[b*Cn + c])*MASK_VAL;
    float nm = fmaxf(m, x);
    s = s*__expf(m - nm) + __expf(x - nm);
    m = nm;
  }
  g_colpm[(b*16 + ch)*Qn + q] = m;
  g_colps[(b*16 + ch)*Qn + q] = s;
}

__global__ void __launch_bounds__(128) k_colcombine(){
  int b = blockIdx.x, q = threadIdx.x;
  float m = -INFINITY, s = 0.f;
  for (int ch = 0; ch < 16; ch++){
    float pm = g_colpm[(b*16 + ch)*Qn + q];
    float ps = g_colps[(b*16 + ch)*Qn + q];
    float nm = fmaxf(m, pm);
    s = s*__expf(m - nm) + ps*__expf(pm - nm);
    m = nm;
  }
  g_colmax[b*Qn + q] = m;
  g_colsum[b*Qn + q] = s;
}

// ---------------- tmp = score_t^T @ V (tf32 single, split-K x4) ----------------
__global__ void __launch_bounds__(256,2) k_tmp(const float* __restrict__ vfeats,
                                               const float* __restrict__ vmask){
  int b = blockIdx.y, ch = blockIdx.x;
  const float* Sb = g_score + (size_t)b*Cn*Qn;
  const float* V  = vfeats  + (size_t)b*Cn*Dn;
  __shared__ float Ah[128][20], Bh[128][20];
  __shared__ float cm[128];
  int tid = threadIdx.x;
  if (tid < 128) cm[tid] = g_colmax[b*Qn + tid];
  __syncthreads();
  int warp = tid >> 5, lane = tid & 31;
  int WM = warp >> 1, WN = warp & 1;
  int grp = lane >> 2, qd = lane & 3;
  int mb = WM*32, nb = WN*64;
  float acc[2][8][4] = {};
  int bkl = tid >> 4, bseg = tid & 15;
  int bcolp = (bkl & 3)*4 + (bkl >> 2);
  int cbase = ch*512;
  for (int kt = 0; kt < 512; kt += 16){
    int c = cbase + kt + bkl;
    float mv = (1.f - vmask[b*Cn + c])*MASK_VAL;
    int e0 = bseg*8;
    {
      const float* src = &Sb[(size_t)c*Qn + e0];
      float4 v0 = *(const float4*)&src[0];
      float4 v1 = *(const float4*)&src[4];
      float vv[8] = {v0.x,v0.y,v0.z,v0.w,v1.x,v1.y,v1.z,v1.w};
      #pragma unroll
      for (int e = 0; e < 8; e++)
        Ah[e0+e][bcolp] = tf32_hi(__expf(vv[e] + mv - cm[e0+e]));
    }
    {
      const float* src = &V[(size_t)c*Dn + e0];
      float4 v0 = *(const float4*)&src[0];
      float4 v1 = *(const float4*)&src[4];
      float vv[8] = {v0.x,v0.y,v0.z,v0.w,v1.x,v1.y,v1.z,v1.w};
      #pragma unroll
      for (int e = 0; e < 8; e++)
        Bh[e0+e][bcolp] = tf32_hi(vv[e]);
    }
    __syncthreads();
    mma_k16(Ah, Bh, acc, mb, nb, grp, qd);
    __syncthreads();
  }
  float* P = g_tmp_part + (size_t)(b*4 + ch)*Qn*Dn;
  #pragma unroll
  for (int mi = 0; mi < 2; mi++){
    int r = mb + mi*16 + grp;
    #pragma unroll
    for (int ni = 0; ni < 8; ni++){
      int col = nb + ni*8 + qd*2;
      *(float2*)&P[(size_t)r*Dn + col]     = make_float2(acc[mi][ni][0], acc[mi][ni][1]);
      *(float2*)&P[(size_t)(r+8)*Dn + col] = make_float2(acc[mi][ni][2], acc[mi][ni][3]);
    }
  }
}

__global__ void __launch_bounds__(256) k_tmp_reduce(){
  int idx = blockIdx.x*256 + threadIdx.x;
  int b = idx >> 14;
  int r = idx & 16383;
  int q = r >> 7;
  size_t base = (size_t)b*4*Qn*Dn + r;
  float s = g_tmp_part[base] + g_tmp_part[base + Qn*Dn]
          + g_tmp_part[base + 2*Qn*Dn] + g_tmp_part[base + 3*Qn*Dn];
  g_tmp[idx] = s / g_colsum[b*Qn + q];
}

// ---------------- P @ B (tf32 residual): W=0: c2q = P@qf, W=1: q2c = P@tmp ----------------
// IMPORTANT: device-global scratch (g_tmp, g_c2q, g_q2c) must be bound INSIDE
// device code — passing __device__ symbols as host-side kernel args gives the
// host shadow address (silently "works" on GB300 via ATS and corrupts results).
template<int W>
__global__ void __launch_bounds__(256,2) k_pgemm(const float* __restrict__ qf,
                                                 const float* __restrict__ qmask){
  int b = blockIdx.y; int m0 = blockIdx.x*128;
  const float* Sb = g_score + (size_t)b*Cn*Qn;
  const float* Bm = (W == 0 ? qf : (const float*)g_tmp) + (size_t)b*Qn*Dn;
  float* O = (W == 0 ? g_c2q : g_q2c) + ((size_t)b*Cn + m0)*Dn;
  __shared__ float Ah[128][20], Al[128][20], Bh[128][20], Bl[128][20];
  __shared__ float qm[128], rm[128], ri[128];
  int tid = threadIdx.x;
  if (tid < 128){
    qm[tid] = (1.f - qmask[b*Qn + tid])*MASK_VAL;
    rm[tid] = g_rowmax[b*Cn + m0 + tid];
    ri[tid] = 1.f / g_rowsum[b*Cn + m0 + tid];
  }
  __syncthreads();
  int warp = tid >> 5, lane = tid & 31;
  int WM = warp >> 1, WN = warp & 1;
  int grp = lane >> 2, qd = lane & 3;
  int mb = WM*32, nb = WN*64;
  float acc[2][8][4] = {};
  int arow = tid >> 1, aj0 = (tid & 1)*2;
  int bkl = tid >> 4, bseg = tid & 15;
  int bcolp = (bkl & 3)*4 + (bkl >> 2);
  float mm = rm[arow], rr = ri[arow];
  for (int k0 = 0; k0 < Qn; k0 += 16){
    #pragma unroll
    for (int jj = 0; jj < 2; jj++){
      int j = aj0 + jj;
      int kg = k0 + j*4;
      float4 v = *(const float4*)&Sb[(size_t)(m0 + arow)*Qn + kg];
      float p, h;
      p = __expf(v.x + qm[kg]   - mm)*rr; h = tf32_hi(p); Ah[arow][0+j]  = h; Al[arow][0+j]  = tf32_hi(p - h);
      p = __expf(v.y + qm[kg+1] - mm)*rr; h = tf32_hi(p); Ah[arow][4+j]  = h; Al[arow][4+j]  = tf32_hi(p - h);
      p = __expf(v.z + qm[kg+2] - mm)*rr; h = tf32_hi(p); Ah[arow][8+j]  = h; Al[arow][8+j]  = tf32_hi(p - h);
      p = __expf(v.w + qm[kg+3] - mm)*rr; h = tf32_hi(p); Ah[arow][12+j] = h; Al[arow][12+j] = tf32_hi(p - h);
    }
    {
      const float* src = &Bm[(size_t)(k0 + bkl)*Dn + bseg*8];
      float4 v0 = *(const float4*)&src[0];
      float4 v1 = *(const float4*)&src[4];
      int n0 = bseg*8;
      float vv[8] = {v0.x,v0.y,v0.z,v0.w,v1.x,v1.y,v1.z,v1.w};
      #pragma unroll
      for (int e = 0; e < 8; e++){
        float h = tf32_hi(vv[e]);
        Bh[n0+e][bcolp] = h; Bl[n0+e][bcolp] = tf32_hi(vv[e]-h);
      }
    }
    __syncthreads();
    mma_k16(Ah, Bh, acc, mb, nb, grp, qd);
    mma_k16(Al, Bh, acc, mb, nb, grp, qd);
    mma_k16(Ah, Bl, acc, mb, nb, grp, qd);
    __syncthreads();
  }
  #pragma unroll
  for (int mi = 0; mi < 2; mi++){
    int r = mb + mi*16 + grp;
    #pragma unroll
    for (int ni = 0; ni < 8; ni++){
      int col = nb + ni*8 + qd*2;
      *(float2*)&O[(size_t)r*Dn + col]     = make_float2(acc[mi][ni][0], acc[mi][ni][1]);
      *(float2*)&O[(size_t)(r+8)*Dn + col] = make_float2(acc[mi][ni][2], acc[mi][ni][3]);
    }
  }
}

// ---------------- feats = [v, c2q, v*c2q, v*q2c] @ cqa_W^T + b (tf32 single) ----------------
__global__ void __launch_bounds__(256,2) k_feats(const float* __restrict__ vfeats,
                                                 const float* __restrict__ cqa_b){
  size_t m0 = (size_t)blockIdx.x*128;
  __shared__ float Ah[128][20], Bh[128][20];
  __shared__ float cb[128];
  int tid = threadIdx.x;
  if (tid < 128) cb[tid] = cqa_b[tid];
  int warp = tid >> 5, lane = tid & 31;
  int WM = warp >> 1, WN = warp & 1;
  int grp = lane >> 2, qd = lane & 3;
  int mb = WM*32, nb = WN*64;
  float acc[2][8][4] = {};
  int arow = tid >> 1, aj0 = (tid & 1)*2;
  int bkl = tid >> 4, bseg = tid & 15;
  int bcolp = (bkl & 3)*4 + (bkl >> 2);
  for (int it = 0; it < 32; it++){
    int src = it >> 3; int kl0 = (it & 7)*16;
    #pragma unroll
    for (int jj = 0; jj < 2; jj++){
      int j = aj0 + jj;
      size_t off = (m0 + arow)*(size_t)Dn + kl0 + j*4;
      float4 v;
      if (src == 0)      v = *(const float4*)&vfeats[off];
      else if (src == 1) v = *(const float4*)&g_c2q[off];
      else if (src == 2){
        float4 a = *(const float4*)&vfeats[off]; float4 c = *(const float4*)&g_c2q[off];
        v = make_float4(a.x*c.x, a.y*c.y, a.z*c.z, a.w*c.w);
      } else {
        float4 a = *(const float4*)&vfeats[off]; float4 c = *(const float4*)&g_q2c[off];
        v = make_float4(a.x*c.x, a.y*c.y, a.z*c.z, a.w*c.w);
      }
      Ah[arow][0+j]  = tf32_hi(v.x);
      Ah[arow][4+j]  = tf32_hi(v.y);
      Ah[arow][8+j]  = tf32_hi(v.z);
      Ah[arow][12+j] = tf32_hi(v.w);
    }
    {
      int kk = it*16 + bkl;
      const float* srcp = &g_cqaWT[kk*128 + bseg*8];
      float4 v0 = *(const float4*)&srcp[0];
      float4 v1 = *(const float4*)&srcp[4];
      int n0 = bseg*8;
      float vv[8] = {v0.x,v0.y,v0.z,v0.w,v1.x,v1.y,v1.z,v1.w};
      #pragma unroll
      for (int e = 0; e < 8; e++) Bh[n0+e][bcolp] = tf32_hi(vv[e]);
    }
    __syncthreads();
    mma_k16(Ah, Bh, acc, mb, nb, grp, qd);
    __syncthreads();
  }
  #pragma unroll
  for (int mi = 0; mi < 2; mi++){
    size_t r = m0 + mb + mi*16 + grp;
    #pragma unroll
    for (int ni = 0; ni < 8; ni++){
      int col = nb + ni*8 + qd*2;
      *(float2*)&g_feats[r*Dn + col]     = make_float2(acc[mi][ni][0] + cb[col], acc[mi][ni][1] + cb[col+1]);
      *(float2*)&g_feats[(r+8)*Dn + col] = make_float2(acc[mi][ni][2] + cb[col], acc[mi][ni][3] + cb[col+1]);
    }
  }
}

// ---------------- out = relu(feats @ ccW1^T + bias2[b]) (tf32 residual) ----------------
__global__ void __launch_bounds__(256,2) k_out(float* __restrict__ out){
  size_t m0 = (size_t)blockIdx.x*128;
  int bb = (int)(m0 >> 11);
  __shared__ float Ah[128][20], Al[128][20], Bh[128][20], Bl[128][20];
  __shared__ float b2s[128];
  int tid = threadIdx.x;
  if (tid < 128) b2s[tid] = g_bias2[bb*Dn + tid];
  int warp = tid >> 5, lane = tid & 31;
  int WM = warp >> 1, WN = warp & 1;
  int grp = lane >> 2, qd = lane & 3;
  int mb = WM*32, nb = WN*64;
  float acc[2][8][4] = {};
  int arow = tid >> 1, aj0 = (tid & 1)*2;
  int bkl = tid >> 4, bseg = tid & 15;
  int bcolp = (bkl & 3)*4 + (bkl >> 2);
  for (int k0 = 0; k0 < 128; k0 += 16){
    #pragma unroll
    for (int jj = 0; jj < 2; jj++){
      int j = aj0 + jj;
      float4 v = *(const float4*)&g_feats[(m0 + arow)*(size_t)Dn + k0 + j*4];
      float h;
      h = tf32_hi(v.x); Ah[arow][0+j]  = h; Al[arow][0+j]  = tf32_hi(v.x - h);
      h = tf32_hi(v.y); Ah[arow][4+j]  = h; Al[arow][4+j]  = tf32_hi(v.y - h);
      h = tf32_hi(v.z); Ah[arow][8+j]  = h; Al[arow][8+j]  = tf32_hi(v.z - h);
      h = tf32_hi(v.w); Ah[arow][12+j] = h; Al[arow][12+j] = tf32_hi(v.w - h);
    }
    {
      const float* src = &g_ccWT[(k0 + bkl)*128 + bseg*8];
      float4 v0 = *(const float4*)&src[0];
      float4 v1 = *(const float4*)&src[4];
      int n0 = bseg*8;
      float vv[8] = {v0.x,v0.y,v0.z,v0.w,v1.x,v1.y,v1.z,v1.w};
      #pragma unroll
      for (int e = 0; e < 8; e++){
        float h = tf32_hi(vv[e]);
        Bh[n0+e][bcolp] = h; Bl[n0+e][bcolp] = tf32_hi(vv[e]-h);
      }
    }
    __syncthreads();
    mma_k16(Ah, Bh, acc, mb, nb, grp, qd);
    mma_k16(Al, Bh, acc, mb, nb, grp, qd);
    mma_k16(Ah, Bl, acc, mb, nb, grp, qd);
    __syncthreads();
  }
  #pragma unroll
  for (int mi = 0; mi < 2; mi++){
    size_t r = m0 + mb + mi*16 + grp;
    #pragma unroll
    for (int ni = 0; ni < 8; ni++){
      int col = nb + ni*8 + qd*2;
      float2 w0 = make_float2(fmaxf(acc[mi][ni][0] + b2s[col], 0.f), fmaxf(acc[mi][ni][1] + b2s[col+1], 0.f));
      float2 w1 = make_float2(fmaxf(acc[mi][ni][2] + b2s[col], 0.f), fmaxf(acc[mi][ni][3] + b2s[col+1], 0.f));
      *(float2*)&out[r*Dn + col]     = w0;
      *(float2*)&out[(r+8)*Dn + col] = w1;
    }
  }
}

// ---------------- launch ----------------
extern "C" void kernel_launch(void* const* d_in, const int* in_sizes, int n_in,
                              void* d_out, int out_size){
  const float* vfeats = (const float*)d_in[0];
  const float* qfeats = (const float*)d_in[1];
  const float* vmask  = (const float*)d_in[2];
  const float* qmask  = (const float*)d_in[3];
  const float* w4C    = (const float*)d_in[4];
  const float* w4Q    = (const float*)d_in[5];
  const float* w4mlu  = (const float*)d_in[6];
  const float* cqa_W  = (const float*)d_in[7];
  const float* cqa_b  = (const float*)d_in[8];
  const float* wp     = (const float*)d_in[9];
  const float* cc_W   = (const float*)d_in[10];
  const float* cc_b   = (const float*)d_in[11];
  float* out = (float*)d_out;

  k_prepW<<<128, 256>>>(cqa_W, cc_W);
  k_beff<<<Bn, 128>>>(qfeats, w4mlu, w4C);
  k_pool<<<Bn, 128>>>(qfeats, w4Q, wp, qmask, cc_W, cc_b);
  k_score<<<dim3(Cn/128, Bn), 256>>>(vfeats);
  k_rowstats<<<(Bn*Cn)/8, 256>>>(qmask);
  k_colstats<<<dim3(16, Bn), 128>>>(vmask);
  k_colcombine<<<Bn, 128>>>();
  k_tmp<<<dim3(4, Bn), 256>>>(vfeats, vmask);
  k_tmp_reduce<<<(Bn*Qn*Dn)/256, 256>>>();
  k_pgemm<0><<<dim3(Cn/128, Bn), 256>>>(qfeats, qmask);
  k_pgemm<1><<<dim3(Cn/128, Bn), 256>>>(qfeats, qmask);
  k_feats<<<(Bn*Cn)/128, 256>>>(vfeats, cqa_b);
  k_out<<<(Bn*Cn)/128, 256>>>(out);
}

// round 7
// speedup vs baseline: 1.4230x; 1.2732x over previous
#include <cuda_runtime.h>
#include <math.h>

#define Bn 64
#define Cn 2048
#define Qn 128
#define Dn 128
#define MASK_VAL (-1e30f)

// ---------------- scratch ----------------
__device__ float g_score[(size_t)Bn*Cn*Qn];
__device__ float g_Beff [(size_t)Bn*Dn*Qn];
__device__ float g_bq   [Bn*Qn];
__device__ float g_rowmax[Bn*Cn];
__device__ float g_rowsum[Bn*Cn];
__device__ float g_colpm[Bn*16*Qn];
__device__ float g_colps[Bn*16*Qn];
__device__ float g_colmax[Bn*Qn];
__device__ float g_colsum[Bn*Qn];
__device__ float g_tmp_part[(size_t)Bn*4*Qn*Dn];
__device__ float g_tmp [(size_t)Bn*Qn*Dn];
__device__ float g_bias2[Bn*Dn];
__device__ float g_c2q [(size_t)Bn*Cn*Dn];
__device__ float g_q2c [(size_t)Bn*Cn*Dn];
__device__ float g_feats[(size_t)Bn*Cn*Dn];
__device__ float g_cqaWT[512*128];
__device__ float g_ccWT [128*128];

// ---------------- tf32 helpers ----------------
__device__ __forceinline__ unsigned cvt_tf32(float x){
  unsigned u; asm("cvt.rna.tf32.f32 %0, %1;" : "=r"(u) : "f"(x)); return u;
}
__device__ __forceinline__ float tf32_hi(float x){ return __uint_as_float(cvt_tf32(x)); }

#define MMA_TF32(D, A0,A1,A2,A3, B0,B1) \
  asm volatile("mma.sync.aligned.m16n8k8.row.col.f32.tf32.tf32.f32 " \
      "{%0,%1,%2,%3}, {%4,%5,%6,%7}, {%8,%9}, {%0,%1,%2,%3};" \
      : "+f"(D[0]), "+f"(D[1]), "+f"(D[2]), "+f"(D[3]) \
      : "r"(A0), "r"(A1), "r"(A2), "r"(A3), "r"(B0), "r"(B1))

// Per-warp 32x64 tile MMA over a k16 chunk.
// As: [128][20] rows=m, cols = permuted k (colp = (k%4)*4 + k/4)
// Bs: [128][20] rows=n, cols = permuted k
__device__ __forceinline__ void mma_k16(const float (*As)[20], const float (*Bs)[20],
                                        float acc[2][8][4], int mb, int nb, int grp, int qd){
  float4 va[2][2];
  #pragma unroll
  for (int mi = 0; mi < 2; mi++){
    int r = mb + mi*16 + grp;
    va[mi][0] = *(const float4*)&As[r][qd*4];
    va[mi][1] = *(const float4*)&As[r+8][qd*4];
  }
  float4 vb[8];
  #pragma unroll
  for (int ni = 0; ni < 8; ni++){
    int n = nb + ni*8 + grp;
    vb[ni] = *(const float4*)&Bs[n][qd*4];
  }
  #pragma unroll
  for (int mi = 0; mi < 2; mi++)
    #pragma unroll
    for (int ni = 0; ni < 8; ni++){
      MMA_TF32(acc[mi][ni],
        __float_as_uint(va[mi][0].x), __float_as_uint(va[mi][1].x),
        __float_as_uint(va[mi][0].y), __float_as_uint(va[mi][1].y),
        __float_as_uint(vb[ni].x),    __float_as_uint(vb[ni].y));
      MMA_TF32(acc[mi][ni],
        __float_as_uint(va[mi][0].z), __float_as_uint(va[mi][1].z),
        __float_as_uint(va[mi][0].w), __float_as_uint(va[mi][1].w),
        __float_as_uint(vb[ni].z),    __float_as_uint(vb[ni].w));
    }
}

// ---------------- prep kernels ----------------
__global__ void k_prepW(const float* __restrict__ cqaW, const float* __restrict__ ccW){
  int tid = blockIdx.x*blockDim.x + threadIdx.x;
  int stride = gridDim.x*blockDim.x;
  for (int idx = tid; idx < 512*128; idx += stride){
    int k = idx >> 7, n = idx & 127;
    g_cqaWT[idx] = cqaW[n*512 + k];
  }
  for (int idx = tid; idx < 128*128; idx += stride){
    int k = idx >> 7, n = idx & 127;
    g_ccWT[idx] = ccW[n*256 + k];
  }
}

__global__ void __launch_bounds__(128) k_beff(const float* __restrict__ qf,
                                              const float* __restrict__ w4mlu,
                                              const float* __restrict__ w4C){
  int b = blockIdx.x, tid = threadIdx.x;
  __shared__ float s[64][129];
  for (int q0 = 0; q0 < Qn; q0 += 64){
    for (int r = 0; r < 64; r++)
      s[r][tid] = qf[((size_t)b*Qn + q0 + r)*Dn + tid];
    __syncthreads();
    for (int it = 0; it < 64; it++){
      int idx = it*128 + tid;
      int d = idx >> 6, q = idx & 63;
      g_Beff[(size_t)b*Dn*Qn + (size_t)d*Qn + q0 + q] = s[q][d]*w4mlu[d] + w4C[d];
    }
    __syncthreads();
  }
}

__global__ void __launch_bounds__(128) k_pool(const float* __restrict__ qf,
                                              const float* __restrict__ w4Q,
                                              const float* __restrict__ wp,
                                              const float* __restrict__ qmask,
                                              const float* __restrict__ ccW,
                                              const float* __restrict__ ccb){
  int b = blockIdx.x, tid = threadIdx.x;
  __shared__ float red[128];
  __shared__ float alpha[128];
  __shared__ float pooled[128];
  const float* qrow = qf + ((size_t)b*Qn + tid)*Dn;
  float bq = 0.f, lg = 0.f;
  for (int d = 0; d < Dn; d++){ float v = qrow[d]; bq += v*w4Q[d]; lg += v*wp[d]; }
  g_bq[b*Qn + tid] = bq;
  float x = lg + (1.f - qmask[b*Qn + tid])*MASK_VAL;
  red[tid] = x; __syncthreads();
  for (int s = 64; s > 0; s >>= 1){ if (tid < s) red[tid] = fmaxf(red[tid], red[tid+s]); __syncthreads(); }
  float m = red[0]; __syncthreads();
  float e = __expf(x - m);
  red[tid] = e; __syncthreads();
  for (int s = 64; s > 0; s >>= 1){ if (tid < s) red[tid] += red[tid+s]; __syncthreads(); }
  float ssum = red[0];
  alpha[tid] = e / ssum;
  __syncthreads();
  float p = 0.f;
  for (int q = 0; q < Qn; q++) p += qf[((size_t)b*Qn + q)*Dn + tid]*alpha[q];
  pooled[tid] = p; __syncthreads();
  float acc = ccb[tid];
  for (int k = 0; k < Dn; k++) acc += pooled[k]*ccW[tid*256 + 128 + k];
  g_bias2[b*Dn + tid] = acc;
}

// ---------------- score GEMM (single tf32, double-buffered) + fused softmax stats ----------------
__global__ void __launch_bounds__(256,2) k_score(const float* __restrict__ vfeats,
                                                 const float* __restrict__ vmask,
                                                 const float* __restrict__ qmask){
  int b  = blockIdx.y, bx = blockIdx.x;
  int m0 = bx*128;
  const float* A  = vfeats + (size_t)b*Cn*Dn;
  const float* Bm = g_Beff + (size_t)b*Dn*Qn;
  float* Sout = g_score + (size_t)b*Cn*Qn;
  __shared__ float As[2][128][20], Bs[2][128][20];
  __shared__ float bqs[128], qm[128], vm[128];
  __shared__ float smRm[128][2], smRs[128][2];
  __shared__ float smCm[128][4], smCs[128][4];
  int tid = threadIdx.x;
  if (tid < 128){
    bqs[tid] = g_bq[b*Qn + tid];
    qm[tid]  = (1.f - qmask[b*Qn + tid])*MASK_VAL;
    vm[tid]  = (1.f - vmask[b*Cn + m0 + tid])*MASK_VAL;
  }
  int arow = tid >> 1, aj0 = (tid & 1)*2;
  int bkl = tid >> 4, bseg = tid & 15;
  int bcolp = (bkl & 3)*4 + (bkl >> 2);
  // preload chunk 0
  #pragma unroll
  for (int jj = 0; jj < 2; jj++){
    int j = aj0 + jj;
    float4 v = *(const float4*)&A[(size_t)(m0 + arow)*Dn + j*4];
    As[0][arow][0+j]  = tf32_hi(v.x); As[0][arow][4+j]  = tf32_hi(v.y);
    As[0][arow][8+j]  = tf32_hi(v.z); As[0][arow][12+j] = tf32_hi(v.w);
  }
  {
    const float* src = &Bm[(size_t)bkl*Qn + bseg*8];
    float4 v0 = *(const float4*)&src[0], v1 = *(const float4*)&src[4];
    int n0 = bseg*8;
    Bs[0][n0+0][bcolp]=tf32_hi(v0.x); Bs[0][n0+1][bcolp]=tf32_hi(v0.y);
    Bs[0][n0+2][bcolp]=tf32_hi(v0.z); Bs[0][n0+3][bcolp]=tf32_hi(v0.w);
    Bs[0][n0+4][bcolp]=tf32_hi(v1.x); Bs[0][n0+5][bcolp]=tf32_hi(v1.y);
    Bs[0][n0+6][bcolp]=tf32_hi(v1.z); Bs[0][n0+7][bcolp]=tf32_hi(v1.w);
  }
  __syncthreads();
  int warp = tid >> 5, lane = tid & 31;
  int WM = warp >> 1, WN = warp & 1;
  int grp = lane >> 2, qd = lane & 3;
  int mb = WM*32, nb = WN*64;
  float acc[2][8][4] = {};
  for (int k0 = 0; k0 < 8; k0++){
    float4 av[2], bv0, bv1;
    bool nxt = (k0 < 7);
    if (nxt){
      int kn = (k0+1)*16;
      av[0] = *(const float4*)&A[(size_t)(m0 + arow)*Dn + kn + aj0*4];
      av[1] = *(const float4*)&A[(size_t)(m0 + arow)*Dn + kn + (aj0+1)*4];
      const float* sp = &Bm[(size_t)(kn + bkl)*Qn + bseg*8];
      bv0 = *(const float4*)&sp[0]; bv1 = *(const float4*)&sp[4];
    }
    mma_k16(As[k0&1], Bs[k0&1], acc, mb, nb, grp, qd);
    if (nxt){
      int nbuf = (k0+1)&1;
      #pragma unroll
      for (int jj = 0; jj < 2; jj++){
        int j = aj0 + jj;
        As[nbuf][arow][0+j]  = tf32_hi(av[jj].x); As[nbuf][arow][4+j]  = tf32_hi(av[jj].y);
        As[nbuf][arow][8+j]  = tf32_hi(av[jj].z); As[nbuf][arow][12+j] = tf32_hi(av[jj].w);
      }
      int n0 = bseg*8;
      Bs[nbuf][n0+0][bcolp]=tf32_hi(bv0.x); Bs[nbuf][n0+1][bcolp]=tf32_hi(bv0.y);
      Bs[nbuf][n0+2][bcolp]=tf32_hi(bv0.z); Bs[nbuf][n0+3][bcolp]=tf32_hi(bv0.w);
      Bs[nbuf][n0+4][bcolp]=tf32_hi(bv1.x); Bs[nbuf][n0+5][bcolp]=tf32_hi(bv1.y);
      Bs[nbuf][n0+6][bcolp]=tf32_hi(bv1.z); Bs[nbuf][n0+7][bcolp]=tf32_hi(bv1.w);
    }
    __syncthreads();
  }
  // ---- epilogue: add bq, write score, fused row/col softmax stats ----
  #pragma unroll
  for (int mi = 0; mi < 2; mi++){
    int r = m0 + mb + mi*16 + grp;
    #pragma unroll
    for (int ni = 0; ni < 8; ni++){
      int c0 = nb + ni*8 + qd*2;
      acc[mi][ni][0] += bqs[c0]; acc[mi][ni][1] += bqs[c0+1];
      acc[mi][ni][2] += bqs[c0]; acc[mi][ni][3] += bqs[c0+1];
      *(float2*)&Sout[(size_t)r*Qn + c0]     = make_float2(acc[mi][ni][0], acc[mi][ni][1]);
      *(float2*)&Sout[(size_t)(r+8)*Qn + c0] = make_float2(acc[mi][ni][2], acc[mi][ni][3]);
    }
  }
  // row stats (each row fully inside block; warp holds 64-col half)
  #pragma unroll
  for (int s = 0; s < 4; s++){
    int mi = s >> 1, e0 = (s & 1)*2;
    float m = -INFINITY;
    #pragma unroll
    for (int ni = 0; ni < 8; ni++){
      int c0 = nb + ni*8 + qd*2;
      m = fmaxf(m, acc[mi][ni][e0]   + qm[c0]);
      m = fmaxf(m, acc[mi][ni][e0+1] + qm[c0+1]);
    }
    m = fmaxf(m, __shfl_xor_sync(0xffffffffu, m, 1));
    m = fmaxf(m, __shfl_xor_sync(0xffffffffu, m, 2));
    float ssum = 0.f;
    #pragma unroll
    for (int ni = 0; ni < 8; ni++){
      int c0 = nb + ni*8 + qd*2;
      ssum += __expf(acc[mi][ni][e0]   + qm[c0]   - m);
      ssum += __expf(acc[mi][ni][e0+1] + qm[c0+1] - m);
    }
    ssum += __shfl_xor_sync(0xffffffffu, ssum, 1);
    ssum += __shfl_xor_sync(0xffffffffu, ssum, 2);
    if (qd == 0){
      int rr = mb + mi*16 + (s & 1)*8 + grp;
      smRm[rr][WN] = m; smRs[rr][WN] = ssum;
    }
  }
  // col stats (partial over this block's 128 rows), processed in groups of 4 cols
  float vmr[4] = { vm[mb+grp], vm[mb+grp+8], vm[mb+16+grp], vm[mb+16+grp+8] };
  #pragma unroll
  for (int g = 0; g < 4; g++){
    float cm4[4], cs4[4];
    #pragma unroll
    for (int u = 0; u < 4; u++){
      int idx = g*4 + u;          // idx = ni*2 + e
      int ni = idx >> 1, e = idx & 1;
      float m = fmaxf(fmaxf(acc[0][ni][e] + vmr[0], acc[0][ni][e+2] + vmr[1]),
                      fmaxf(acc[1][ni][e] + vmr[2], acc[1][ni][e+2] + vmr[3]));
      cm4[u] = m;
    }
    #pragma unroll
    for (int o = 4; o <= 16; o <<= 1)
      #pragma unroll
      for (int u = 0; u < 4; u++)
        cm4[u] = fmaxf(cm4[u], __shfl_xor_sync(0xffffffffu, cm4[u], o));
    #pragma unroll
    for (int u = 0; u < 4; u++){
      int idx = g*4 + u;
      int ni = idx >> 1, e = idx & 1;
      cs4[u] = __expf(acc[0][ni][e]   + vmr[0] - cm4[u])
             + __expf(acc[0][ni][e+2] + vmr[1] - cm4[u])
             + __expf(acc[1][ni][e]   + vmr[2] - cm4[u])
             + __expf(acc[1][ni][e+2] + vmr[3] - cm4[u]);
    }
    #pragma unroll
    for (int o = 4; o <= 16; o <<= 1)
      #pragma unroll
      for (int u = 0; u < 4; u++)
        cs4[u] += __shfl_xor_sync(0xffffffffu, cs4[u], o);
    if (grp == 0){
      #pragma unroll
      for (int u = 0; u < 4; u++){
        int idx = g*4 + u;
        int ni = idx >> 1, e = idx & 1;
        int col = nb + ni*8 + qd*2 + e;
        smCm[col][WM] = cm4[u]; smCs[col][WM] = cs4[u];
      }
    }
  }
  __syncthreads();
  if (tid < 128){
    float ma = smRm[tid][0], mbv = smRm[tid][1];
    float M = fmaxf(ma, mbv);
    float S = smRs[tid][0]*__expf(ma - M) + smRs[tid][1]*__expf(mbv - M);
    g_rowmax[b*Cn + m0 + tid] = M;
    g_rowsum[b*Cn + m0 + tid] = S;
    float cm2 = -INFINITY, cs2 = 0.f;
    #pragma unroll
    for (int w = 0; w < 4; w++){
      float pm = smCm[tid][w], ps = smCs[tid][w];
      float nm = fmaxf(cm2, pm);
      cs2 = cs2*__expf(cm2 - nm) + ps*__expf(pm - nm);
      cm2 = nm;
    }
    g_colpm[(b*16 + bx)*Qn + tid] = cm2;
    g_colps[(b*16 + bx)*Qn + tid] = cs2;
  }
}

__global__ void __launch_bounds__(128) k_colcombine(){
  int b = blockIdx.x, q = threadIdx.x;
  float m = -INFINITY, s = 0.f;
  for (int ch = 0; ch < 16; ch++){
    float pm = g_colpm[(b*16 + ch)*Qn + q];
    float ps = g_colps[(b*16 + ch)*Qn + q];
    float nm = fmaxf(m, pm);
    s = s*__expf(m - nm) + ps*__expf(pm - nm);
    m = nm;
  }
  g_colmax[b*Qn + q] = m;
  g_colsum[b*Qn + q] = s;
}

// ---------------- tmp = score_t^T @ V (single tf32, split-K x4, double-buffered) ----------------
__global__ void __launch_bounds__(256,2) k_tmp(const float* __restrict__ vfeats,
                                               const float* __restrict__ vmask){
  int b = blockIdx.y, ch = blockIdx.x;
  const float* Sb = g_score + (size_t)b*Cn*Qn;
  const float* V  = vfeats  + (size_t)b*Cn*Dn;
  __shared__ float As[2][128][20], Bs[2][128][20];
  __shared__ float cm[128];
  int tid = threadIdx.x;
  if (tid < 128) cm[tid] = g_colmax[b*Qn + tid];
  __syncthreads();
  int bkl = tid >> 4, bseg = tid & 15;
  int bcolp = (bkl & 3)*4 + (bkl >> 2);
  int e0 = bseg*8;
  int cbase = ch*512;
  // preload chunk 0
  {
    int c = cbase + bkl;
    float mv = (1.f - vmask[b*Cn + c])*MASK_VAL;
    float4 s0 = *(const float4*)&Sb[(size_t)c*Qn + e0];
    float4 s1 = *(const float4*)&Sb[(size_t)c*Qn + e0 + 4];
    As[0][e0+0][bcolp]=tf32_hi(__expf(s0.x+mv-cm[e0+0])); As[0][e0+1][bcolp]=tf32_hi(__expf(s0.y+mv-cm[e0+1]));
    As[0][e0+2][bcolp]=tf32_hi(__expf(s0.z+mv-cm[e0+2])); As[0][e0+3][bcolp]=tf32_hi(__expf(s0.w+mv-cm[e0+3]));
    As[0][e0+4][bcolp]=tf32_hi(__expf(s1.x+mv-cm[e0+4])); As[0][e0+5][bcolp]=tf32_hi(__expf(s1.y+mv-cm[e0+5]));
    As[0][e0+6][bcolp]=tf32_hi(__expf(s1.z+mv-cm[e0+6])); As[0][e0+7][bcolp]=tf32_hi(__expf(s1.w+mv-cm[e0+7]));
    float4 v0 = *(const float4*)&V[(size_t)c*Dn + e0];
    float4 v1 = *(const float4*)&V[(size_t)c*Dn + e0 + 4];
    Bs[0][e0+0][bcolp]=tf32_hi(v0.x); Bs[0][e0+1][bcolp]=tf32_hi(v0.y);
    Bs[0][e0+2][bcolp]=tf32_hi(v0.z); Bs[0][e0+3][bcolp]=tf32_hi(v0.w);
    Bs[0][e0+4][bcolp]=tf32_hi(v1.x); Bs[0][e0+5][bcolp]=tf32_hi(v1.y);
    Bs[0][e0+6][bcolp]=tf32_hi(v1.z); Bs[0][e0+7][bcolp]=tf32_hi(v1.w);
  }
  __syncthreads();
  int warp = tid >> 5, lane = tid & 31;
  int WM = warp >> 1, WN = warp & 1;
  int grp = lane >> 2, qd = lane & 3;
  int mb = WM*32, nb = WN*64;
  float acc[2][8][4] = {};
  for (int kt = 0; kt < 32; kt++){
    float4 s0n, s1n, v0n, v1n; float mvn = 0.f;
    bool nxt = (kt < 31);
    if (nxt){
      int c = cbase + (kt+1)*16 + bkl;
      mvn = (1.f - vmask[b*Cn + c])*MASK_VAL;
      s0n = *(const float4*)&Sb[(size_t)c*Qn + e0];
      s1n = *(const float4*)&Sb[(size_t)c*Qn + e0 + 4];
      v0n = *(const float4*)&V[(size_t)c*Dn + e0];
      v1n = *(const float4*)&V[(size_t)c*Dn + e0 + 4];
    }
    mma_k16(As[kt&1], Bs[kt&1], acc, mb, nb, grp, qd);
    if (nxt){
      int nbuf = (kt+1)&1;
      As[nbuf][e0+0][bcolp]=tf32_hi(__expf(s0n.x+mvn-cm[e0+0])); As[nbuf][e0+1][bcolp]=tf32_hi(__expf(s0n.y+mvn-cm[e0+1]));
      As[nbuf][e0+2][bcolp]=tf32_hi(__expf(s0n.z+mvn-cm[e0+2])); As[nbuf][e0+3][bcolp]=tf32_hi(__expf(s0n.w+mvn-cm[e0+3]));
      As[nbuf][e0+4][bcolp]=tf32_hi(__expf(s1n.x+mvn-cm[e0+4])); As[nbuf][e0+5][bcolp]=tf32_hi(__expf(s1n.y+mvn-cm[e0+5]));
      As[nbuf][e0+6][bcolp]=tf32_hi(__expf(s1n.z+mvn-cm[e0+6])); As[nbuf][e0+7][bcolp]=tf32_hi(__expf(s1n.w+mvn-cm[e0+7]));
      Bs[nbuf][e0+0][bcolp]=tf32_hi(v0n.x); Bs[nbuf][e0+1][bcolp]=tf32_hi(v0n.y);
      Bs[nbuf][e0+2][bcolp]=tf32_hi(v0n.z); Bs[nbuf][e0+3][bcolp]=tf32_hi(v0n.w);
      Bs[nbuf][e0+4][bcolp]=tf32_hi(v1n.x); Bs[nbuf][e0+5][bcolp]=tf32_hi(v1n.y);
      Bs[nbuf][e0+6][bcolp]=tf32_hi(v1n.z); Bs[nbuf][e0+7][bcolp]=tf32_hi(v1n.w);
    }
    __syncthreads();
  }
  float* P = g_tmp_part + (size_t)(b*4 + ch)*Qn*Dn;
  #pragma unroll
  for (int mi = 0; mi < 2; mi++){
    int r = mb + mi*16 + grp;
    #pragma unroll
    for (int ni = 0; ni < 8; ni++){
      int col = nb + ni*8 + qd*2;
      *(float2*)&P[(size_t)r*Dn + col]     = make_float2(acc[mi][ni][0], acc[mi][ni][1]);
      *(float2*)&P[(size_t)(r+8)*Dn + col] = make_float2(acc[mi][ni][2], acc[mi][ni][3]);
    }
  }
}

__global__ void __launch_bounds__(256) k_tmp_reduce(){
  int idx = blockIdx.x*256 + threadIdx.x;
  int b = idx >> 14;
  int r = idx & 16383;
  int q = r >> 7;
  size_t base = (size_t)b*4*Qn*Dn + r;
  float s = g_tmp_part[base] + g_tmp_part[base + Qn*Dn]
          + g_tmp_part[base + 2*Qn*Dn] + g_tmp_part[base + 3*Qn*Dn];
  g_tmp[idx] = s / g_colsum[b*Qn + q];
}

// ---------------- P @ B (single tf32, db): W=0: c2q = P@qf, W=1: q2c = P@tmp ----------------
// Device-global scratch bound INSIDE device code (host-side __device__ symbol args
// silently resolve to host shadows on GB300/ATS).
template<int W>
__global__ void __launch_bounds__(256,2) k_pgemm(const float* __restrict__ qf,
                                                 const float* __restrict__ qmask){
  int b = blockIdx.y; int m0 = blockIdx.x*128;
  const float* Sb = g_score + (size_t)b*Cn*Qn;
  const float* Bm = (W == 0 ? qf : (const float*)g_tmp) + (size_t)b*Qn*Dn;
  float* O = (W == 0 ? g_c2q : g_q2c) + ((size_t)b*Cn + m0)*Dn;
  __shared__ float As[2][128][20], Bs[2][128][20];
  __shared__ float qm[128], rm[128], ri[128];
  int tid = threadIdx.x;
  if (tid < 128){
    qm[tid] = (1.f - qmask[b*Qn + tid])*MASK_VAL;
    rm[tid] = g_rowmax[b*Cn + m0 + tid];
    ri[tid] = 1.f / g_rowsum[b*Cn + m0 + tid];
  }
  __syncthreads();
  int arow = tid >> 1, aj0 = (tid & 1)*2;
  int bkl = tid >> 4, bseg = tid & 15;
  int bcolp = (bkl & 3)*4 + (bkl >> 2);
  float mm = rm[arow], rr = ri[arow];
  // preload chunk 0
  #pragma unroll
  for (int jj = 0; jj < 2; jj++){
    int j = aj0 + jj;
    int kg = j*4;
    float4 v = *(const float4*)&Sb[(size_t)(m0 + arow)*Qn + kg];
    As[0][arow][0+j]  = tf32_hi(__expf(v.x + qm[kg]   - mm)*rr);
    As[0][arow][4+j]  = tf32_hi(__expf(v.y + qm[kg+1] - mm)*rr);
    As[0][arow][8+j]  = tf32_hi(__expf(v.z + qm[kg+2] - mm)*rr);
    As[0][arow][12+j] = tf32_hi(__expf(v.w + qm[kg+3] - mm)*rr);
  }
  {
    const float* src = &Bm[(size_t)bkl*Dn + bseg*8];
    float4 v0 = *(const float4*)&src[0], v1 = *(const float4*)&src[4];
    int n0 = bseg*8;
    Bs[0][n0+0][bcolp]=tf32_hi(v0.x); Bs[0][n0+1][bcolp]=tf32_hi(v0.y);
    Bs[0][n0+2][bcolp]=tf32_hi(v0.z); Bs[0][n0+3][bcolp]=tf32_hi(v0.w);
    Bs[0][n0+4][bcolp]=tf32_hi(v1.x); Bs[0][n0+5][bcolp]=tf32_hi(v1.y);
    Bs[0][n0+6][bcolp]=tf32_hi(v1.z); Bs[0][n0+7][bcolp]=tf32_hi(v1.w);
  }
  __syncthreads();
  int warp = tid >> 5, lane = tid & 31;
  int WM = warp >> 1, WN = warp & 1;
  int grp = lane >> 2, qd = lane & 3;
  int mb = WM*32, nb = WN*64;
  float acc[2][8][4] = {};
  for (int k0 = 0; k0 < 8; k0++){
    float4 av[2], bv0, bv1;
    bool nxt = (k0 < 7);
    if (nxt){
      int kn = (k0+1)*16;
      av[0] = *(const float4*)&Sb[(size_t)(m0 + arow)*Qn + kn + aj0*4];
      av[1] = *(const float4*)&Sb[(size_t)(m0 + arow)*Qn + kn + (aj0+1)*4];
      const float* sp = &Bm[(size_t)(kn + bkl)*Dn + bseg*8];
      bv0 = *(const float4*)&sp[0]; bv1 = *(const float4*)&sp[4];
    }
    mma_k16(As[k0&1], Bs[k0&1], acc, mb, nb, grp, qd);
    if (nxt){
      int nbuf = (k0+1)&1;
      int kn = (k0+1)*16;
      #pragma unroll
      for (int jj = 0; jj < 2; jj++){
        int j = aj0 + jj;
        int kg = kn + j*4;
        As[nbuf][arow][0+j]  = tf32_hi(__expf(av[jj].x + qm[kg]   - mm)*rr);
        As[nbuf][arow][4+j]  = tf32_hi(__expf(av[jj].y + qm[kg+1] - mm)*rr);
        As[nbuf][arow][8+j]  = tf32_hi(__expf(av[jj].z + qm[kg+2] - mm)*rr);
        As[nbuf][arow][12+j] = tf32_hi(__expf(av[jj].w + qm[kg+3] - mm)*rr);
      }
      int n0 = bseg*8;
      Bs[nbuf][n0+0][bcolp]=tf32_hi(bv0.x); Bs[nbuf][n0+1][bcolp]=tf32_hi(bv0.y);
      Bs[nbuf][n0+2][bcolp]=tf32_hi(bv0.z); Bs[nbuf][n0+3][bcolp]=tf32_hi(bv0.w);
      Bs[nbuf][n0+4][bcolp]=tf32_hi(bv1.x); Bs[nbuf][n0+5][bcolp]=tf32_hi(bv1.y);
      Bs[nbuf][n0+6][bcolp]=tf32_hi(bv1.z); Bs[nbuf][n0+7][bcolp]=tf32_hi(bv1.w);
    }
    __syncthreads();
  }
  #pragma unroll
  for (int mi = 0; mi < 2; mi++){
    int r = mb + mi*16 + grp;
    #pragma unroll
    for (int ni = 0; ni < 8; ni++){
      int col = nb + ni*8 + qd*2;
      *(float2*)&O[(size_t)r*Dn + col]     = make_float2(acc[mi][ni][0], acc[mi][ni][1]);
      *(float2*)&O[(size_t)(r+8)*Dn + col] = make_float2(acc[mi][ni][2], acc[mi][ni][3]);
    }
  }
}

// ---------------- feats = [v, c2q, v*c2q, v*q2c] @ cqa_W^T + b (single tf32, db) ----------------
__global__ void __launch_bounds__(256,2) k_feats(const float* __restrict__ vfeats,
                                                 const float* __restrict__ cqa_b){
  size_t m0 = (size_t)blockIdx.x*128;
  __shared__ float As[2][128][20], Bs[2][128][20];
  __shared__ float cb[128];
  int tid = threadIdx.x;
  if (tid < 128) cb[tid] = cqa_b[tid];
  int arow = tid >> 1, aj0 = (tid & 1)*2;
  int bkl = tid >> 4, bseg = tid & 15;
  int bcolp = (bkl & 3)*4 + (bkl >> 2);
  // preload chunk 0 (src=0 -> vfeats)
  #pragma unroll
  for (int jj = 0; jj < 2; jj++){
    int j = aj0 + jj;
    float4 v = *(const float4*)&vfeats[(m0 + arow)*(size_t)Dn + j*4];
    As[0][arow][0+j]  = tf32_hi(v.x); As[0][arow][4+j]  = tf32_hi(v.y);
    As[0][arow][8+j]  = tf32_hi(v.z); As[0][arow][12+j] = tf32_hi(v.w);
  }
  {
    const float* srcp = &g_cqaWT[bkl*128 + bseg*8];
    float4 v0 = *(const float4*)&srcp[0], v1 = *(const float4*)&srcp[4];
    int n0 = bseg*8;
    Bs[0][n0+0][bcolp]=tf32_hi(v0.x); Bs[0][n0+1][bcolp]=tf32_hi(v0.y);
    Bs[0][n0+2][bcolp]=tf32_hi(v0.z); Bs[0][n0+3][bcolp]=tf32_hi(v0.w);
    Bs[0][n0+4][bcolp]=tf32_hi(v1.x); Bs[0][n0+5][bcolp]=tf32_hi(v1.y);
    Bs[0][n0+6][bcolp]=tf32_hi(v1.z); Bs[0][n0+7][bcolp]=tf32_hi(v1.w);
  }
  __syncthreads();
  int warp = tid >> 5, lane = tid & 31;
  int WM = warp >> 1, WN = warp & 1;
  int grp = lane >> 2, qd = lane & 3;
  int mb = WM*32, nb = WN*64;
  float acc[2][8][4] = {};
  for (int it = 0; it < 32; it++){
    float4 av[2], cv[2], bv0, bv1;
    int src2 = (it+1) >> 3;
    bool nxt = (it < 31);
    if (nxt){
      int kl2 = ((it+1) & 7)*16;
      #pragma unroll
      for (int jj = 0; jj < 2; jj++){
        size_t off = (m0 + arow)*(size_t)Dn + kl2 + (aj0+jj)*4;
        if (src2 == 0)      { av[jj] = *(const float4*)&vfeats[off]; }
        else if (src2 == 1) { av[jj] = *(const float4*)&g_c2q[off]; }
        else if (src2 == 2) { av[jj] = *(const float4*)&vfeats[off]; cv[jj] = *(const float4*)&g_c2q[off]; }
        else                { av[jj] = *(const float4*)&vfeats[off]; cv[jj] = *(const float4*)&g_q2c[off]; }
      }
      const float* sp = &g_cqaWT[((it+1)*16 + bkl)*128 + bseg*8];
      bv0 = *(const float4*)&sp[0]; bv1 = *(const float4*)&sp[4];
    }
    mma_k16(As[it&1], Bs[it&1], acc, mb, nb, grp, qd);
    if (nxt){
      int nbuf = (it+1)&1;
      #pragma unroll
      for (int jj = 0; jj < 2; jj++){
        int j = aj0 + jj;
        float4 v = av[jj];
        if (src2 >= 2){ v.x *= cv[jj].x; v.y *= cv[jj].y; v.z *= cv[jj].z; v.w *= cv[jj].w; }
        As[nbuf][arow][0+j]  = tf32_hi(v.x); As[nbuf][arow][4+j]  = tf32_hi(v.y);
        As[nbuf][arow][8+j]  = tf32_hi(v.z); As[nbuf][arow][12+j] = tf32_hi(v.w);
      }
      int n0 = bseg*8;
      Bs[nbuf][n0+0][bcolp]=tf32_hi(bv0.x); Bs[nbuf][n0+1][bcolp]=tf32_hi(bv0.y);
      Bs[nbuf][n0+2][bcolp]=tf32_hi(bv0.z); Bs[nbuf][n0+3][bcolp]=tf32_hi(bv0.w);
      Bs[nbuf][n0+4][bcolp]=tf32_hi(bv1.x); Bs[nbuf][n0+5][bcolp]=tf32_hi(bv1.y);
      Bs[nbuf][n0+6][bcolp]=tf32_hi(bv1.z); Bs[nbuf][n0+7][bcolp]=tf32_hi(bv1.w);
    }
    __syncthreads();
  }
  #pragma unroll
  for (int mi = 0; mi < 2; mi++){
    size_t r = m0 + mb + mi*16 + grp;
    #pragma unroll
    for (int ni = 0; ni < 8; ni++){
      int col = nb + ni*8 + qd*2;
      *(float2*)&g_feats[r*Dn + col]     = make_float2(acc[mi][ni][0] + cb[col], acc[mi][ni][1] + cb[col+1]);
      *(float2*)&g_feats[(r+8)*Dn + col] = make_float2(acc[mi][ni][2] + cb[col], acc[mi][ni][3] + cb[col+1]);
    }
  }
}

// ---------------- out = relu(feats @ ccW1^T + bias2[b]) (single tf32, db) ----------------
__global__ void __launch_bounds__(256,2) k_out(float* __restrict__ out){
  size_t m0 = (size_t)blockIdx.x*128;
  int bb = (int)(m0 >> 11);
  __shared__ float As[2][128][20], Bs[2][128][20];
  __shared__ float b2s[128];
  int tid = threadIdx.x;
  if (tid < 128) b2s[tid] = g_bias2[bb*Dn + tid];
  int arow = tid >> 1, aj0 = (tid & 1)*2;
  int bkl = tid >> 4, bseg = tid & 15;
  int bcolp = (bkl & 3)*4 + (bkl >> 2);
  // preload chunk 0
  #pragma unroll
  for (int jj = 0; jj < 2; jj++){
    int j = aj0 + jj;
    float4 v = *(const float4*)&g_feats[(m0 + arow)*(size_t)Dn + j*4];
    As[0][arow][0+j]  = tf32_hi(v.x); As[0][arow][4+j]  = tf32_hi(v.y);
    As[0][arow][8+j]  = tf32_hi(v.z); As[0][arow][12+j] = tf32_hi(v.w);
  }
  {
    const float* src = &g_ccWT[bkl*128 + bseg*8];
    float4 v0 = *(const float4*)&src[0], v1 = *(const float4*)&src[4];
    int n0 = bseg*8;
    Bs[0][n0+0][bcolp]=tf32_hi(v0.x); Bs[0][n0+1][bcolp]=tf32_hi(v0.y);
    Bs[0][n0+2][bcolp]=tf32_hi(v0.z); Bs[0][n0+3][bcolp]=tf32_hi(v0.w);
    Bs[0][n0+4][bcolp]=tf32_hi(v1.x); Bs[0][n0+5][bcolp]=tf32_hi(v1.y);
    Bs[0][n0+6][bcolp]=tf32_hi(v1.z); Bs[0][n0+7][bcolp]=tf32_hi(v1.w);
  }
  __syncthreads();
  int warp = tid >> 5, lane = tid & 31;
  int WM = warp >> 1, WN = warp & 1;
  int grp = lane >> 2, qd = lane & 3;
  int mb = WM*32, nb = WN*64;
  float acc[2][8][4] = {};
  for (int k0 = 0; k0 < 8; k0++){
    float4 av[2], bv0, bv1;
    bool nxt = (k0 < 7);
    if (nxt){
      int kn = (k0+1)*16;
      av[0] = *(const float4*)&g_feats[(m0 + arow)*(size_t)Dn + kn + aj0*4];
      av[1] = *(const float4*)&g_feats[(m0 + arow)*(size_t)Dn + kn + (aj0+1)*4];
      const float* sp = &g_ccWT[(kn + bkl)*128 + bseg*8];
      bv0 = *(const float4*)&sp[0]; bv1 = *(const float4*)&sp[4];
    }
    mma_k16(As[k0&1], Bs[k0&1], acc, mb, nb, grp, qd);
    if (nxt){
      int nbuf = (k0+1)&1;
      #pragma unroll
      for (int jj = 0; jj < 2; jj++){
        int j = aj0 + jj;
        As[nbuf][arow][0+j]  = tf32_hi(av[jj].x); As[nbuf][arow][4+j]  = tf32_hi(av[jj].y);
        As[nbuf][arow][8+j]  = tf32_hi(av[jj].z); As[nbuf][arow][12+j] = tf32_hi(av[jj].w);
      }
      int n0 = bseg*8;
      Bs[nbuf][n0+0][bcolp]=tf32_hi(bv0.x); Bs[nbuf][n0+1][bcolp]=tf32_hi(bv0.y);
      Bs[nbuf][n0+2][bcolp]=tf32_hi(bv0.z); Bs[nbuf][n0+3][bcolp]=tf32_hi(bv0.w);
      Bs[nbuf][n0+4][bcolp]=tf32_hi(bv1.x); Bs[nbuf][n0+5][bcolp]=tf32_hi(bv1.y);
      Bs[nbuf][n0+6][bcolp]=tf32_hi(bv1.z); Bs[nbuf][n0+7][bcolp]=tf32_hi(bv1.w);
    }
    __syncthreads();
  }
  #pragma unroll
  for (int mi = 0; mi < 2; mi++){
    size_t r = m0 + mb + mi*16 + grp;
    #pragma unroll
    for (int ni = 0; ni < 8; ni++){
      int col = nb + ni*8 + qd*2;
      float2 w0 = make_float2(fmaxf(acc[mi][ni][0] + b2s[col], 0.f), fmaxf(acc[mi][ni][1] + b2s[col+1], 0.f));
      float2 w1 = make_float2(fmaxf(acc[mi][ni][2] + b2s[col], 0.f), fmaxf(acc[mi][ni][3] + b2s[col+1], 0.f));
      *(float2*)&out[r*Dn + col]     = w0;
      *(float2*)&out[(r+8)*Dn + col] = w1;
    }
  }
}

// ---------------- launch ----------------
extern "C" void kernel_launch(void* const* d_in, const int* in_sizes, int n_in,
                              void* d_out, int out_size){
  const float* vfeats = (const float*)d_in[0];
  const float* qfeats = (const float*)d_in[1];
  const float* vmask  = (const float*)d_in[2];
  const float* qmask  = (const float*)d_in[3];
  const float* w4C    = (const float*)d_in[4];
  const float* w4Q    = (const float*)d_in[5];
  const float* w4mlu  = (const float*)d_in[6];
  const float* cqa_W  = (const float*)d_in[7];
  const float* cqa_b  = (const float*)d_in[8];
  const float* wp     = (const float*)d_in[9];
  const float* cc_W   = (const float*)d_in[10];
  const float* cc_b   = (const float*)d_in[11];
  float* out = (float*)d_out;

  k_prepW<<<128, 256>>>(cqa_W, cc_W);
  k_beff<<<Bn, 128>>>(qfeats, w4mlu, w4C);
  k_pool<<<Bn, 128>>>(qfeats, w4Q, wp, qmask, cc_W, cc_b);
  k_score<<<dim3(Cn/128, Bn), 256>>>(vfeats, vmask, qmask);
  k_colcombine<<<Bn, 128>>>();
  k_tmp<<<dim3(4, Bn), 256>>>(vfeats, vmask);
  k_tmp_reduce<<<(Bn*Qn*Dn)/256, 256>>>();
  k_pgemm<0><<<dim3(Cn/128, Bn), 256>>>(qfeats, qmask);
  k_pgemm<1><<<dim3(Cn/128, Bn), 256>>>(qfeats, qmask);
  k_feats<<<(Bn*Cn)/128, 256>>>(vfeats, cqa_b);
  k_out<<<(Bn*Cn)/128, 256>>>(out);
}

// round 8
// speedup vs baseline: 1.8530x; 1.3022x over previous
#include <cuda_runtime.h>
#include <math.h>

#define Bn 64
#define Cn 2048
#define Qn 128
#define Dn 128
#define MASK_VAL (-1e30f)

// ---------------- scratch ----------------
__device__ float g_score[(size_t)Bn*Cn*Qn];
__device__ float g_Beff [(size_t)Bn*Dn*Qn];
__device__ float g_bq   [Bn*Qn];
__device__ float g_rowmax[Bn*Cn];
__device__ float g_rowsum[Bn*Cn];
__device__ float g_colpm[Bn*16*Qn];
__device__ float g_colps[Bn*16*Qn];
__device__ float g_colmax[Bn*Qn];
__device__ float g_colsum[Bn*Qn];
__device__ float g_tmp_part[(size_t)Bn*4*Qn*Dn];
__device__ float g_tmp [(size_t)Bn*Qn*Dn];
__device__ float g_bias2[Bn*Dn];
__device__ float g_c2q [(size_t)Bn*Cn*Dn];
__device__ float g_q2c [(size_t)Bn*Cn*Dn];
__device__ float g_feats[(size_t)Bn*Cn*Dn];
__device__ float g_cqaWT[512*128];
__device__ float g_ccWT [128*128];

// ---------------- tf32 helpers ----------------
__device__ __forceinline__ unsigned cvt_tf32(float x){
  unsigned u; asm("cvt.rna.tf32.f32 %0, %1;" : "=r"(u) : "f"(x)); return u;
}
__device__ __forceinline__ float tf32_hi(float x){ return __uint_as_float(cvt_tf32(x)); }

#define MMA_TF32(D, A0,A1,A2,A3, B0,B1) \
  asm volatile("mma.sync.aligned.m16n8k8.row.col.f32.tf32.tf32.f32 " \
      "{%0,%1,%2,%3}, {%4,%5,%6,%7}, {%8,%9}, {%0,%1,%2,%3};" \
      : "+f"(D[0]), "+f"(D[1]), "+f"(D[2]), "+f"(D[3]) \
      : "r"(A0), "r"(A1), "r"(A2), "r"(A3), "r"(B0), "r"(B1))

// ---- swizzled fragment tile [128][32]:
// element k (0..15) of row n stored at quad ((k&3) + (n&7) + (n>>3)) & 7, offset k>>2.
// Fragment float4 at quad ((qd + (n&7) + (n>>3)) & 7) holds k = {qd, qd+4, qd+8, qd+12}.

// B-producer: thread owns k=bkl, 8 consecutive rows n = bseg*8 + e. 2-phase stores.
__device__ __forceinline__ void storeB8(float (*T)[32], int bseg, int bkl, const float* v8){
  int bq = bkl >> 2, bc = bkl & 3;
  int e0 = bseg*8;
  #pragma unroll
  for (int e = 0; e < 8; e++)
    T[e0+e][((bc + e + bseg) & 7)*4 + bq] = v8[e];
}
// A-producer: thread owns row arow, k-quads j = aj0, aj0+1 (each float4 = k j*4..j*4+3).
__device__ __forceinline__ void storeA2(float (*T)[32], int arow, int aj0,
                                        const float4& v0, const float4& v1){
  int ga = (arow & 7) + (arow >> 3);
  const float* p0 = (const float*)&v0;
  const float* p1 = (const float*)&v1;
  #pragma unroll
  for (int t = 0; t < 4; t++){
    T[arow][((t + ga) & 7)*4 + aj0]     = p0[t];
    T[arow][((t + ga) & 7)*4 + aj0 + 1] = p1[t];
  }
}

// Per-warp 32x64 tile MMA over a k16 chunk, swizzled tiles.
__device__ __forceinline__ void mma_k16(const float (*As)[32], const float (*Bs)[32],
                                        float acc[2][8][4], int mb, int nb, int grp, int qd){
  int baseq = qd + grp;
  int mh = mb >> 3, nh = nb >> 3;
  float4 va[2][2];
  #pragma unroll
  for (int mi = 0; mi < 2; mi++){
    int r = mb + mi*16 + grp;
    va[mi][0] = *(const float4*)&As[r][((baseq + mh + mi*2) & 7)*4];
    va[mi][1] = *(const float4*)&As[r+8][((baseq + mh + mi*2 + 1) & 7)*4];
  }
  float4 vb[8];
  #pragma unroll
  for (int ni = 0; ni < 8; ni++){
    int n = nb + ni*8 + grp;
    vb[ni] = *(const float4*)&Bs[n][((baseq + nh + ni) & 7)*4];
  }
  #pragma unroll
  for (int mi = 0; mi < 2; mi++)
    #pragma unroll
    for (int ni = 0; ni < 8; ni++){
      MMA_TF32(acc[mi][ni],
        __float_as_uint(va[mi][0].x), __float_as_uint(va[mi][1].x),
        __float_as_uint(va[mi][0].y), __float_as_uint(va[mi][1].y),
        __float_as_uint(vb[ni].x),    __float_as_uint(vb[ni].y));
      MMA_TF32(acc[mi][ni],
        __float_as_uint(va[mi][0].z), __float_as_uint(va[mi][1].z),
        __float_as_uint(va[mi][0].w), __float_as_uint(va[mi][1].w),
        __float_as_uint(vb[ni].z),    __float_as_uint(vb[ni].w));
    }
}

__device__ __forceinline__ float4 tf4(float4 v){
  return make_float4(tf32_hi(v.x), tf32_hi(v.y), tf32_hi(v.z), tf32_hi(v.w));
}

// ---------------- prep kernels ----------------
__global__ void k_prepW(const float* __restrict__ cqaW, const float* __restrict__ ccW){
  int tid = blockIdx.x*blockDim.x + threadIdx.x;
  int stride = gridDim.x*blockDim.x;
  for (int idx = tid; idx < 512*128; idx += stride){
    int k = idx >> 7, n = idx & 127;
    g_cqaWT[idx] = cqaW[n*512 + k];
  }
  for (int idx = tid; idx < 128*128; idx += stride){
    int k = idx >> 7, n = idx & 127;
    g_ccWT[idx] = ccW[n*256 + k];
  }
}

__global__ void __launch_bounds__(128) k_beff(const float* __restrict__ qf,
                                              const float* __restrict__ w4mlu,
                                              const float* __restrict__ w4C){
  int b = blockIdx.x, tid = threadIdx.x;
  __shared__ float s[64][129];
  for (int q0 = 0; q0 < Qn; q0 += 64){
    for (int r = 0; r < 64; r++)
      s[r][tid] = qf[((size_t)b*Qn + q0 + r)*Dn + tid];
    __syncthreads();
    for (int it = 0; it < 64; it++){
      int idx = it*128 + tid;
      int d = idx >> 6, q = idx & 63;
      g_Beff[(size_t)b*Dn*Qn + (size_t)d*Qn + q0 + q] = s[q][d]*w4mlu[d] + w4C[d];
    }
    __syncthreads();
  }
}

__global__ void __launch_bounds__(128) k_pool(const float* __restrict__ qf,
                                              const float* __restrict__ w4Q,
                                              const float* __restrict__ wp,
                                              const float* __restrict__ qmask,
                                              const float* __restrict__ ccW,
                                              const float* __restrict__ ccb){
  int b = blockIdx.x, tid = threadIdx.x;
  __shared__ float red[128];
  __shared__ float alpha[128];
  __shared__ float pooled[128];
  const float* qrow = qf + ((size_t)b*Qn + tid)*Dn;
  float bq = 0.f, lg = 0.f;
  for (int d = 0; d < Dn; d++){ float v = qrow[d]; bq += v*w4Q[d]; lg += v*wp[d]; }
  g_bq[b*Qn + tid] = bq;
  float x = lg + (1.f - qmask[b*Qn + tid])*MASK_VAL;
  red[tid] = x; __syncthreads();
  for (int s = 64; s > 0; s >>= 1){ if (tid < s) red[tid] = fmaxf(red[tid], red[tid+s]); __syncthreads(); }
  float m = red[0]; __syncthreads();
  float e = __expf(x - m);
  red[tid] = e; __syncthreads();
  for (int s = 64; s > 0; s >>= 1){ if (tid < s) red[tid] += red[tid+s]; __syncthreads(); }
  float ssum = red[0];
  alpha[tid] = e / ssum;
  __syncthreads();
  float p = 0.f;
  for (int q = 0; q < Qn; q++) p += qf[((size_t)b*Qn + q)*Dn + tid]*alpha[q];
  pooled[tid] = p; __syncthreads();
  float acc = ccb[tid];
  for (int k = 0; k < Dn; k++) acc += pooled[k]*ccW[tid*256 + 128 + k];
  g_bias2[b*Dn + tid] = acc;
}

// ---------------- score GEMM (tf32, db, swizzled) + fused softmax stats ----------------
__global__ void __launch_bounds__(256,2) k_score(const float* __restrict__ vfeats,
                                                 const float* __restrict__ vmask,
                                                 const float* __restrict__ qmask){
  int b  = blockIdx.y, bx = blockIdx.x;
  int m0 = bx*128;
  const float* A  = vfeats + (size_t)b*Cn*Dn;
  const float* Bm = g_Beff + (size_t)b*Dn*Qn;
  float* Sout = g_score + (size_t)b*Cn*Qn;
  __shared__ float As[2][128][32], Bs[2][128][32];
  __shared__ float bqs[128], qm[128], vm[128];
  __shared__ float smRm[128][2], smRs[128][2];
  __shared__ float smCm[128][4], smCs[128][4];
  int tid = threadIdx.x;
  if (tid < 128){
    bqs[tid] = g_bq[b*Qn + tid];
    qm[tid]  = (1.f - qmask[b*Qn + tid])*MASK_VAL;
    vm[tid]  = (1.f - vmask[b*Cn + m0 + tid])*MASK_VAL;
  }
  int arow = tid >> 1, aj0 = (tid & 1)*2;
  int bkl = tid >> 4, bseg = tid & 15;
  // preload chunk 0
  {
    float4 v0 = tf4(*(const float4*)&A[(size_t)(m0 + arow)*Dn + aj0*4]);
    float4 v1 = tf4(*(const float4*)&A[(size_t)(m0 + arow)*Dn + aj0*4 + 4]);
    storeA2(As[0], arow, aj0, v0, v1);
    const float* src = &Bm[(size_t)bkl*Qn + bseg*8];
    float4 w0 = *(const float4*)&src[0], w1 = *(const float4*)&src[4];
    float vv[8] = {tf32_hi(w0.x),tf32_hi(w0.y),tf32_hi(w0.z),tf32_hi(w0.w),
                   tf32_hi(w1.x),tf32_hi(w1.y),tf32_hi(w1.z),tf32_hi(w1.w)};
    storeB8(Bs[0], bseg, bkl, vv);
  }
  __syncthreads();
  int warp = tid >> 5, lane = tid & 31;
  int WM = warp >> 1, WN = warp & 1;
  int grp = lane >> 2, qd = lane & 3;
  int mb = WM*32, nb = WN*64;
  float acc[2][8][4] = {};
  for (int k0 = 0; k0 < 8; k0++){
    float4 av0, av1, bv0, bv1;
    bool nxt = (k0 < 7);
    if (nxt){
      int kn = (k0+1)*16;
      av0 = *(const float4*)&A[(size_t)(m0 + arow)*Dn + kn + aj0*4];
      av1 = *(const float4*)&A[(size_t)(m0 + arow)*Dn + kn + aj0*4 + 4];
      const float* sp = &Bm[(size_t)(kn + bkl)*Qn + bseg*8];
      bv0 = *(const float4*)&sp[0]; bv1 = *(const float4*)&sp[4];
    }
    mma_k16(As[k0&1], Bs[k0&1], acc, mb, nb, grp, qd);
    if (nxt){
      int nbuf = (k0+1)&1;
      storeA2(As[nbuf], arow, aj0, tf4(av0), tf4(av1));
      float vv[8] = {tf32_hi(bv0.x),tf32_hi(bv0.y),tf32_hi(bv0.z),tf32_hi(bv0.w),
                     tf32_hi(bv1.x),tf32_hi(bv1.y),tf32_hi(bv1.z),tf32_hi(bv1.w)};
      storeB8(Bs[nbuf], bseg, bkl, vv);
    }
    __syncthreads();
  }
  // ---- epilogue: add bq, write score, fused row/col softmax stats ----
  #pragma unroll
  for (int mi = 0; mi < 2; mi++){
    int r = m0 + mb + mi*16 + grp;
    #pragma unroll
    for (int ni = 0; ni < 8; ni++){
      int c0 = nb + ni*8 + qd*2;
      acc[mi][ni][0] += bqs[c0]; acc[mi][ni][1] += bqs[c0+1];
      acc[mi][ni][2] += bqs[c0]; acc[mi][ni][3] += bqs[c0+1];
      *(float2*)&Sout[(size_t)r*Qn + c0]     = make_float2(acc[mi][ni][0], acc[mi][ni][1]);
      *(float2*)&Sout[(size_t)(r+8)*Qn + c0] = make_float2(acc[mi][ni][2], acc[mi][ni][3]);
    }
  }
  // row stats
  #pragma unroll
  for (int s = 0; s < 4; s++){
    int mi = s >> 1, e0 = (s & 1)*2;
    float m = -INFINITY;
    #pragma unroll
    for (int ni = 0; ni < 8; ni++){
      int c0 = nb + ni*8 + qd*2;
      m = fmaxf(m, acc[mi][ni][e0]   + qm[c0]);
      m = fmaxf(m, acc[mi][ni][e0+1] + qm[c0+1]);
    }
    m = fmaxf(m, __shfl_xor_sync(0xffffffffu, m, 1));
    m = fmaxf(m, __shfl_xor_sync(0xffffffffu, m, 2));
    float ssum = 0.f;
    #pragma unroll
    for (int ni = 0; ni < 8; ni++){
      int c0 = nb + ni*8 + qd*2;
      ssum += __expf(acc[mi][ni][e0]   + qm[c0]   - m);
      ssum += __expf(acc[mi][ni][e0+1] + qm[c0+1] - m);
    }
    ssum += __shfl_xor_sync(0xffffffffu, ssum, 1);
    ssum += __shfl_xor_sync(0xffffffffu, ssum, 2);
    if (qd == 0){
      int rr = mb + mi*16 + (s & 1)*8 + grp;
      smRm[rr][WN] = m; smRs[rr][WN] = ssum;
    }
  }
  // col stats (partial over this block's 128 rows)
  float vmr[4] = { vm[mb+grp], vm[mb+grp+8], vm[mb+16+grp], vm[mb+16+grp+8] };
  #pragma unroll
  for (int g = 0; g < 4; g++){
    float cm4[4], cs4[4];
    #pragma unroll
    for (int u = 0; u < 4; u++){
      int idx = g*4 + u;
      int ni = idx >> 1, e = idx & 1;
      float m = fmaxf(fmaxf(acc[0][ni][e] + vmr[0], acc[0][ni][e+2] + vmr[1]),
                      fmaxf(acc[1][ni][e] + vmr[2], acc[1][ni][e+2] + vmr[3]));
      cm4[u] = m;
    }
    #pragma unroll
    for (int o = 4; o <= 16; o <<= 1)
      #pragma unroll
      for (int u = 0; u < 4; u++)
        cm4[u] = fmaxf(cm4[u], __shfl_xor_sync(0xffffffffu, cm4[u], o));
    #pragma unroll
    for (int u = 0; u < 4; u++){
      int idx = g*4 + u;
      int ni = idx >> 1, e = idx & 1;
      cs4[u] = __expf(acc[0][ni][e]   + vmr[0] - cm4[u])
             + __expf(acc[0][ni][e+2] + vmr[1] - cm4[u])
             + __expf(acc[1][ni][e]   + vmr[2] - cm4[u])
             + __expf(acc[1][ni][e+2] + vmr[3] - cm4[u]);
    }
    #pragma unroll
    for (int o = 4; o <= 16; o <<= 1)
      #pragma unroll
      for (int u = 0; u < 4; u++)
        cs4[u] += __shfl_xor_sync(0xffffffffu, cs4[u], o);
    if (grp == 0){
      #pragma unroll
      for (int u = 0; u < 4; u++){
        int idx = g*4 + u;
        int ni = idx >> 1, e = idx & 1;
        int col = nb + ni*8 + qd*2 + e;
        smCm[col][WM] = cm4[u]; smCs[col][WM] = cs4[u];
      }
    }
  }
  __syncthreads();
  if (tid < 128){
    float ma = smRm[tid][0], mbv = smRm[tid][1];
    float M = fmaxf(ma, mbv);
    float S = smRs[tid][0]*__expf(ma - M) + smRs[tid][1]*__expf(mbv - M);
    g_rowmax[b*Cn + m0 + tid] = M;
    g_rowsum[b*Cn + m0 + tid] = S;
    float cm2 = -INFINITY, cs2 = 0.f;
    #pragma unroll
    for (int w = 0; w < 4; w++){
      float pm = smCm[tid][w], ps = smCs[tid][w];
      float nm = fmaxf(cm2, pm);
      cs2 = cs2*__expf(cm2 - nm) + ps*__expf(pm - nm);
      cm2 = nm;
    }
    g_colpm[(b*16 + bx)*Qn + tid] = cm2;
    g_colps[(b*16 + bx)*Qn + tid] = cs2;
  }
}

__global__ void __launch_bounds__(128) k_colcombine(){
  int b = blockIdx.x, q = threadIdx.x;
  float m = -INFINITY, s = 0.f;
  for (int ch = 0; ch < 16; ch++){
    float pm = g_colpm[(b*16 + ch)*Qn + q];
    float ps = g_colps[(b*16 + ch)*Qn + q];
    float nm = fmaxf(m, pm);
    s = s*__expf(m - nm) + ps*__expf(pm - nm);
    m = nm;
  }
  g_colmax[b*Qn + q] = m;
  g_colsum[b*Qn + q] = s;
}

// ---------------- tmp = score_t^T @ V (tf32, split-K x4, db, swizzled) ----------------
__global__ void __launch_bounds__(256,2) k_tmp(const float* __restrict__ vfeats,
                                               const float* __restrict__ vmask){
  int b = blockIdx.y, ch = blockIdx.x;
  const float* Sb = g_score + (size_t)b*Cn*Qn;
  const float* V  = vfeats  + (size_t)b*Cn*Dn;
  __shared__ float As[2][128][32], Bs[2][128][32];
  __shared__ float cm[128];
  int tid = threadIdx.x;
  if (tid < 128) cm[tid] = g_colmax[b*Qn + tid];
  __syncthreads();
  int bkl = tid >> 4, bseg = tid & 15;
  int e0 = bseg*8;
  int cbase = ch*512;
  // preload chunk 0
  {
    int c = cbase + bkl;
    float mv = (1.f - vmask[b*Cn + c])*MASK_VAL;
    float4 s0 = *(const float4*)&Sb[(size_t)c*Qn + e0];
    float4 s1 = *(const float4*)&Sb[(size_t)c*Qn + e0 + 4];
    float av[8] = {tf32_hi(__expf(s0.x+mv-cm[e0+0])), tf32_hi(__expf(s0.y+mv-cm[e0+1])),
                   tf32_hi(__expf(s0.z+mv-cm[e0+2])), tf32_hi(__expf(s0.w+mv-cm[e0+3])),
                   tf32_hi(__expf(s1.x+mv-cm[e0+4])), tf32_hi(__expf(s1.y+mv-cm[e0+5])),
                   tf32_hi(__expf(s1.z+mv-cm[e0+6])), tf32_hi(__expf(s1.w+mv-cm[e0+7]))};
    storeB8(As[0], bseg, bkl, av);
    float4 v0 = *(const float4*)&V[(size_t)c*Dn + e0];
    float4 v1 = *(const float4*)&V[(size_t)c*Dn + e0 + 4];
    float bv[8] = {tf32_hi(v0.x),tf32_hi(v0.y),tf32_hi(v0.z),tf32_hi(v0.w),
                   tf32_hi(v1.x),tf32_hi(v1.y),tf32_hi(v1.z),tf32_hi(v1.w)};
    storeB8(Bs[0], bseg, bkl, bv);
  }
  __syncthreads();
  int warp = tid >> 5, lane = tid & 31;
  int WM = warp >> 1, WN = warp & 1;
  int grp = lane >> 2, qd = lane & 3;
  int mb = WM*32, nb = WN*64;
  float acc[2][8][4] = {};
  for (int kt = 0; kt < 32; kt++){
    float4 s0n, s1n, v0n, v1n; float mvn = 0.f;
    bool nxt = (kt < 31);
    if (nxt){
      int c = cbase + (kt+1)*16 + bkl;
      mvn = (1.f - vmask[b*Cn + c])*MASK_VAL;
      s0n = *(const float4*)&Sb[(size_t)c*Qn + e0];
      s1n = *(const float4*)&Sb[(size_t)c*Qn + e0 + 4];
      v0n = *(const float4*)&V[(size_t)c*Dn + e0];
      v1n = *(const float4*)&V[(size_t)c*Dn + e0 + 4];
    }
    mma_k16(As[kt&1], Bs[kt&1], acc, mb, nb, grp, qd);
    if (nxt){
      int nbuf = (kt+1)&1;
      float av[8] = {tf32_hi(__expf(s0n.x+mvn-cm[e0+0])), tf32_hi(__expf(s0n.y+mvn-cm[e0+1])),
                     tf32_hi(__expf(s0n.z+mvn-cm[e0+2])), tf32_hi(__expf(s0n.w+mvn-cm[e0+3])),
                     tf32_hi(__expf(s1n.x+mvn-cm[e0+4])), tf32_hi(__expf(s1n.y+mvn-cm[e0+5])),
                     tf32_hi(__expf(s1n.z+mvn-cm[e0+6])), tf32_hi(__expf(s1n.w+mvn-cm[e0+7]))};
      storeB8(As[nbuf], bseg, bkl, av);
      float bv[8] = {tf32_hi(v0n.x),tf32_hi(v0n.y),tf32_hi(v0n.z),tf32_hi(v0n.w),
                     tf32_hi(v1n.x),tf32_hi(v1n.y),tf32_hi(v1n.z),tf32_hi(v1n.w)};
      storeB8(Bs[nbuf], bseg, bkl, bv);
    }
    __syncthreads();
  }
  float* P = g_tmp_part + (size_t)(b*4 + ch)*Qn*Dn;
  #pragma unroll
  for (int mi = 0; mi < 2; mi++){
    int r = mb + mi*16 + grp;
    #pragma unroll
    for (int ni = 0; ni < 8; ni++){
      int col = nb + ni*8 + qd*2;
      *(float2*)&P[(size_t)r*Dn + col]     = make_float2(acc[mi][ni][0], acc[mi][ni][1]);
      *(float2*)&P[(size_t)(r+8)*Dn + col] = make_float2(acc[mi][ni][2], acc[mi][ni][3]);
    }
  }
}

__global__ void __launch_bounds__(256) k_tmp_reduce(){
  int idx = blockIdx.x*256 + threadIdx.x;
  int b = idx >> 14;
  int r = idx & 16383;
  int q = r >> 7;
  size_t base = (size_t)b*4*Qn*Dn + r;
  float s = g_tmp_part[base] + g_tmp_part[base + Qn*Dn]
          + g_tmp_part[base + 2*Qn*Dn] + g_tmp_part[base + 3*Qn*Dn];
  g_tmp[idx] = s / g_colsum[b*Qn + q];
}

// ---------------- P @ B (tf32, db, swizzled): W=0: c2q = P@qf, W=1: q2c = P@tmp ----------------
// Device-global scratch bound INSIDE device code (host-side __device__ symbol args
// silently resolve to host shadows on GB300/ATS).
template<int W>
__global__ void __launch_bounds__(256,2) k_pgemm(const float* __restrict__ qf,
                                                 const float* __restrict__ qmask){
  int b = blockIdx.y; int m0 = blockIdx.x*128;
  const float* Sb = g_score + (size_t)b*Cn*Qn;
  const float* Bm = (W == 0 ? qf : (const float*)g_tmp) + (size_t)b*Qn*Dn;
  float* O = (W == 0 ? g_c2q : g_q2c) + ((size_t)b*Cn + m0)*Dn;
  __shared__ float As[2][128][32], Bs[2][128][32];
  __shared__ float qm[128], rm[128], ri[128];
  int tid = threadIdx.x;
  if (tid < 128){
    qm[tid] = (1.f - qmask[b*Qn + tid])*MASK_VAL;
    rm[tid] = g_rowmax[b*Cn + m0 + tid];
    ri[tid] = 1.f / g_rowsum[b*Cn + m0 + tid];
  }
  __syncthreads();
  int arow = tid >> 1, aj0 = (tid & 1)*2;
  int bkl = tid >> 4, bseg = tid & 15;
  float mm = rm[arow], rr = ri[arow];
  // preload chunk 0
  {
    int kg = aj0*4;
    float4 v = *(const float4*)&Sb[(size_t)(m0 + arow)*Qn + kg];
    float4 w = *(const float4*)&Sb[(size_t)(m0 + arow)*Qn + kg + 4];
    float4 a0 = make_float4(tf32_hi(__expf(v.x + qm[kg]   - mm)*rr),
                            tf32_hi(__expf(v.y + qm[kg+1] - mm)*rr),
                            tf32_hi(__expf(v.z + qm[kg+2] - mm)*rr),
                            tf32_hi(__expf(v.w + qm[kg+3] - mm)*rr));
    float4 a1 = make_float4(tf32_hi(__expf(w.x + qm[kg+4] - mm)*rr),
                            tf32_hi(__expf(w.y + qm[kg+5] - mm)*rr),
                            tf32_hi(__expf(w.z + qm[kg+6] - mm)*rr),
                            tf32_hi(__expf(w.w + qm[kg+7] - mm)*rr));
    storeA2(As[0], arow, aj0, a0, a1);
    const float* src = &Bm[(size_t)bkl*Dn + bseg*8];
    float4 w0 = *(const float4*)&src[0], w1 = *(const float4*)&src[4];
    float bv[8] = {tf32_hi(w0.x),tf32_hi(w0.y),tf32_hi(w0.z),tf32_hi(w0.w),
                   tf32_hi(w1.x),tf32_hi(w1.y),tf32_hi(w1.z),tf32_hi(w1.w)};
    storeB8(Bs[0], bseg, bkl, bv);
  }
  __syncthreads();
  int warp = tid >> 5, lane = tid & 31;
  int WM = warp >> 1, WN = warp & 1;
  int grp = lane >> 2, qd = lane & 3;
  int mb = WM*32, nb = WN*64;
  float acc[2][8][4] = {};
  for (int k0 = 0; k0 < 8; k0++){
    float4 av0, av1, bv0, bv1;
    bool nxt = (k0 < 7);
    if (nxt){
      int kn = (k0+1)*16;
      av0 = *(const float4*)&Sb[(size_t)(m0 + arow)*Qn + kn + aj0*4];
      av1 = *(const float4*)&Sb[(size_t)(m0 + arow)*Qn + kn + aj0*4 + 4];
      const float* sp = &Bm[(size_t)(kn + bkl)*Dn + bseg*8];
      bv0 = *(const float4*)&sp[0]; bv1 = *(const float4*)&sp[4];
    }
    mma_k16(As[k0&1], Bs[k0&1], acc, mb, nb, grp, qd);
    if (nxt){
      int nbuf = (k0+1)&1;
      int kg = (k0+1)*16 + aj0*4;
      float4 a0 = make_float4(tf32_hi(__expf(av0.x + qm[kg]   - mm)*rr),
                              tf32_hi(__expf(av0.y + qm[kg+1] - mm)*rr),
                              tf32_hi(__expf(av0.z + qm[kg+2] - mm)*rr),
                              tf32_hi(__expf(av0.w + qm[kg+3] - mm)*rr));
      float4 a1 = make_float4(tf32_hi(__expf(av1.x + qm[kg+4] - mm)*rr),
                              tf32_hi(__expf(av1.y + qm[kg+5] - mm)*rr),
                              tf32_hi(__expf(av1.z + qm[kg+6] - mm)*rr),
                              tf32_hi(__expf(av1.w + qm[kg+7] - mm)*rr));
      storeA2(As[nbuf], arow, aj0, a0, a1);
      float bv[8] = {tf32_hi(bv0.x),tf32_hi(bv0.y),tf32_hi(bv0.z),tf32_hi(bv0.w),
                     tf32_hi(bv1.x),tf32_hi(bv1.y),tf32_hi(bv1.z),tf32_hi(bv1.w)};
      storeB8(Bs[nbuf], bseg, bkl, bv);
    }
    __syncthreads();
  }
  #pragma unroll
  for (int mi = 0; mi < 2; mi++){
    int r = mb + mi*16 + grp;
    #pragma unroll
    for (int ni = 0; ni < 8; ni++){
      int col = nb + ni*8 + qd*2;
      *(float2*)&O[(size_t)r*Dn + col]     = make_float2(acc[mi][ni][0], acc[mi][ni][1]);
      *(float2*)&O[(size_t)(r+8)*Dn + col] = make_float2(acc[mi][ni][2], acc[mi][ni][3]);
    }
  }
}

// ---------------- feats = [v, c2q, v*c2q, v*q2c] @ cqa_W^T + b (tf32, db, swizzled) ----------------
__global__ void __launch_bounds__(256,2) k_feats(const float* __restrict__ vfeats,
                                                 const float* __restrict__ cqa_b){
  size_t m0 = (size_t)blockIdx.x*128;
  __shared__ float As[2][128][32], Bs[2][128][32];
  __shared__ float cb[128];
  int tid = threadIdx.x;
  if (tid < 128) cb[tid] = cqa_b[tid];
  int arow = tid >> 1, aj0 = (tid & 1)*2;
  int bkl = tid >> 4, bseg = tid & 15;
  // preload chunk 0 (src=0 -> vfeats)
  {
    float4 v0 = tf4(*(const float4*)&vfeats[(m0 + arow)*(size_t)Dn + aj0*4]);
    float4 v1 = tf4(*(const float4*)&vfeats[(m0 + arow)*(size_t)Dn + aj0*4 + 4]);
    storeA2(As[0], arow, aj0, v0, v1);
    const float* srcp = &g_cqaWT[bkl*128 + bseg*8];
    float4 w0 = *(const float4*)&srcp[0], w1 = *(const float4*)&srcp[4];
    float bv[8] = {tf32_hi(w0.x),tf32_hi(w0.y),tf32_hi(w0.z),tf32_hi(w0.w),
                   tf32_hi(w1.x),tf32_hi(w1.y),tf32_hi(w1.z),tf32_hi(w1.w)};
    storeB8(Bs[0], bseg, bkl, bv);
  }
  __syncthreads();
  int warp = tid >> 5, lane = tid & 31;
  int WM = warp >> 1, WN = warp & 1;
  int grp = lane >> 2, qd = lane & 3;
  int mb = WM*32, nb = WN*64;
  float acc[2][8][4] = {};
  for (int it = 0; it < 32; it++){
    float4 av0, av1, cv0, cv1, bv0, bv1;
    int src2 = (it+1) >> 3;
    bool nxt = (it < 31);
    if (nxt){
      int kl2 = ((it+1) & 7)*16;
      size_t off0 = (m0 + arow)*(size_t)Dn + kl2 + aj0*4;
      if (src2 == 0)      { av0 = *(const float4*)&vfeats[off0]; av1 = *(const float4*)&vfeats[off0+4]; }
      else if (src2 == 1) { av0 = *(const float4*)&g_c2q[off0];  av1 = *(const float4*)&g_c2q[off0+4]; }
      else if (src2 == 2) { av0 = *(const float4*)&vfeats[off0]; av1 = *(const float4*)&vfeats[off0+4];
                            cv0 = *(const float4*)&g_c2q[off0];  cv1 = *(const float4*)&g_c2q[off0+4]; }
      else                { av0 = *(const float4*)&vfeats[off0]; av1 = *(const float4*)&vfeats[off0+4];
                            cv0 = *(const float4*)&g_q2c[off0];  cv1 = *(const float4*)&g_q2c[off0+4]; }
      const float* sp = &g_cqaWT[((it+1)*16 + bkl)*128 + bseg*8];
      bv0 = *(const float4*)&sp[0]; bv1 = *(const float4*)&sp[4];
    }
    mma_k16(As[it&1], Bs[it&1], acc, mb, nb, grp, qd);
    if (nxt){
      int nbuf = (it+1)&1;
      if (src2 >= 2){
        av0.x *= cv0.x; av0.y *= cv0.y; av0.z *= cv0.z; av0.w *= cv0.w;
        av1.x *= cv1.x; av1.y *= cv1.y; av1.z *= cv1.z; av1.w *= cv1.w;
      }
      storeA2(As[nbuf], arow, aj0, tf4(av0), tf4(av1));
      float bv[8] = {tf32_hi(bv0.x),tf32_hi(bv0.y),tf32_hi(bv0.z),tf32_hi(bv0.w),
                     tf32_hi(bv1.x),tf32_hi(bv1.y),tf32_hi(bv1.z),tf32_hi(bv1.w)};
      storeB8(Bs[nbuf], bseg, bkl, bv);
    }
    __syncthreads();
  }
  #pragma unroll
  for (int mi = 0; mi < 2; mi++){
    size_t r = m0 + mb + mi*16 + grp;
    #pragma unroll
    for (int ni = 0; ni < 8; ni++){
      int col = nb + ni*8 + qd*2;
      *(float2*)&g_feats[r*Dn + col]     = make_float2(acc[mi][ni][0] + cb[col], acc[mi][ni][1] + cb[col+1]);
      *(float2*)&g_feats[(r+8)*Dn + col] = make_float2(acc[mi][ni][2] + cb[col], acc[mi][ni][3] + cb[col+1]);
    }
  }
}

// ---------------- out = relu(feats @ ccW1^T + bias2[b]) (tf32, db, swizzled) ----------------
__global__ void __launch_bounds__(256,2) k_out(float* __restrict__ out){
  size_t m0 = (size_t)blockIdx.x*128;
  int bb = (int)(m0 >> 11);
  __shared__ float As[2][128][32], Bs[2][128][32];
  __shared__ float b2s[128];
  int tid = threadIdx.x;
  if (tid < 128) b2s[tid] = g_bias2[bb*Dn + tid];
  int arow = tid >> 1, aj0 = (tid & 1)*2;
  int bkl = tid >> 4, bseg = tid & 15;
  // preload chunk 0
  {
    float4 v0 = tf4(*(const float4*)&g_feats[(m0 + arow)*(size_t)Dn + aj0*4]);
    float4 v1 = tf4(*(const float4*)&g_feats[(m0 + arow)*(size_t)Dn + aj0*4 + 4]);
    storeA2(As[0], arow, aj0, v0, v1);
    const float* src = &g_ccWT[bkl*128 + bseg*8];
    float4 w0 = *(const float4*)&src[0], w1 = *(const float4*)&src[4];
    float bv[8] = {tf32_hi(w0.x),tf32_hi(w0.y),tf32_hi(w0.z),tf32_hi(w0.w),
                   tf32_hi(w1.x),tf32_hi(w1.y),tf32_hi(w1.z),tf32_hi(w1.w)};
    storeB8(Bs[0], bseg, bkl, bv);
  }
  __syncthreads();
  int warp = tid >> 5, lane = tid & 31;
  int WM = warp >> 1, WN = warp & 1;
  int grp = lane >> 2, qd = lane & 3;
  int mb = WM*32, nb = WN*64;
  float acc[2][8][4] = {};
  for (int k0 = 0; k0 < 8; k0++){
    float4 av0, av1, bv0, bv1;
    bool nxt = (k0 < 7);
    if (nxt){
      int kn = (k0+1)*16;
      av0 = *(const float4*)&g_feats[(m0 + arow)*(size_t)Dn + kn + aj0*4];
      av1 = *(const float4*)&g_feats[(m0 + arow)*(size_t)Dn + kn + aj0*4 + 4];
      const float* sp = &g_ccWT[(kn + bkl)*128 + bseg*8];
      bv0 = *(const float4*)&sp[0]; bv1 = *(const float4*)&sp[4];
    }
    mma_k16(As[k0&1], Bs[k0&1], acc, mb, nb, grp, qd);
    if (nxt){
      int nbuf = (k0+1)&1;
      storeA2(As[nbuf], arow, aj0, tf4(av0), tf4(av1));
      float bv[8] = {tf32_hi(bv0.x),tf32_hi(bv0.y),tf32_hi(bv0.z),tf32_hi(bv0.w),
                     tf32_hi(bv1.x),tf32_hi(bv1.y),tf32_hi(bv1.z),tf32_hi(bv1.w)};
      storeB8(Bs[nbuf], bseg, bkl, bv);
    }
    __syncthreads();
  }
  #pragma unroll
  for (int mi = 0; mi < 2; mi++){
    size_t r = m0 + mb + mi*16 + grp;
    #pragma unroll
    for (int ni = 0; ni < 8; ni++){
      int col = nb + ni*8 + qd*2;
      float2 w0 = make_float2(fmaxf(acc[mi][ni][0] + b2s[col], 0.f), fmaxf(acc[mi][ni][1] + b2s[col+1], 0.f));
      float2 w1 = make_float2(fmaxf(acc[mi][ni][2] + b2s[col], 0.f), fmaxf(acc[mi][ni][3] + b2s[col+1], 0.f));
      *(float2*)&out[r*Dn + col]     = w0;
      *(float2*)&out[(r+8)*Dn + col] = w1;
    }
  }
}

// ---------------- launch ----------------
extern "C" void kernel_launch(void* const* d_in, const int* in_sizes, int n_in,
                              void* d_out, int out_size){
  const float* vfeats = (const float*)d_in[0];
  const float* qfeats = (const float*)d_in[1];
  const float* vmask  = (const float*)d_in[2];
  const float* qmask  = (const float*)d_in[3];
  const float* w4C    = (const float*)d_in[4];
  const float* w4Q    = (const float*)d_in[5];
  const float* w4mlu  = (const float*)d_in[6];
  const float* cqa_W  = (const float*)d_in[7];
  const float* cqa_b  = (const float*)d_in[8];
  const float* wp     = (const float*)d_in[9];
  const float* cc_W   = (const float*)d_in[10];
  const float* cc_b   = (const float*)d_in[11];
  float* out = (float*)d_out;

  k_prepW<<<128, 256>>>(cqa_W, cc_W);
  k_beff<<<Bn, 128>>>(qfeats, w4mlu, w4C);
  k_pool<<<Bn, 128>>>(qfeats, w4Q, wp, qmask, cc_W, cc_b);
  k_score<<<dim3(Cn/128, Bn), 256>>>(vfeats, vmask, qmask);
  k_colcombine<<<Bn, 128>>>();
  k_tmp<<<dim3(4, Bn), 256>>>(vfeats, vmask);
  k_tmp_reduce<<<(Bn*Qn*Dn)/256, 256>>>();
  k_pgemm<0><<<dim3(Cn/128, Bn), 256>>>(qfeats, qmask);
  k_pgemm<1><<<dim3(Cn/128, Bn), 256>>>(qfeats, qmask);
  k_feats<<<(Bn*Cn)/128, 256>>>(vfeats, cqa_b);
  k_out<<<(Bn*Cn)/128, 256>>>(out);
}